// round 2
// baseline (speedup 1.0000x reference)
#include <cuda_runtime.h>

// OuterProduct_45191645888851 — fused MLP + quadratic form.
// Key identity: value[b] = -( x[b] · MLP(x[b]) )^2  (since A = z z^T).
//
// Inputs (metadata order): x[65536,64], W1[512,64], b1[512], W2[512,512], b2[512],
//                          W3[256,512], b3[256], W4[64,256], b4[64]
// Output: float[65536]

#define TB        32     // batch rows per block
#define NTHREADS  256
#define XSTRIDE   68     // padded row stride for the x tile (16B aligned, avoids worst bank conflicts)

// Dynamic smem layout: sA[TB*512] | sB[TB*512] | xs[TB*XSTRIDE]
static __host__ __device__ constexpr int SMEM_FLOATS = TB * 512 * 2 + TB * XSTRIDE;

template<int K, int N, int INSTRIDE, bool ELU>
__device__ __forceinline__ void layer(const float* __restrict__ sIn,
                                      float* __restrict__ sOut,
                                      const float* __restrict__ W,
                                      const float* __restrict__ b,
                                      int tid)
{
    constexpr int CPT = N / 64;            // columns per thread
    const int c  = tid & 63;               // column group 0..63
    const int r0 = (tid >> 6) * 8;         // first of 8 rows handled by this thread

    float acc[8][CPT];
#pragma unroll
    for (int j = 0; j < CPT; j++) {
        float bv = b[c + j * 64];
#pragma unroll
        for (int i = 0; i < 8; i++) acc[i][j] = bv;
    }

#pragma unroll 2
    for (int k = 0; k < K; k += 4) {
        float4 a[8];
#pragma unroll
        for (int i = 0; i < 8; i++)
            a[i] = *reinterpret_cast<const float4*>(&sIn[(r0 + i) * INSTRIDE + k]);

        float4 w[CPT];
#pragma unroll
        for (int j = 0; j < CPT; j++)
            w[j] = *reinterpret_cast<const float4*>(&W[(c + j * 64) * K + k]);

#pragma unroll
        for (int i = 0; i < 8; i++) {
#pragma unroll
            for (int j = 0; j < CPT; j++) {
                acc[i][j] = fmaf(a[i].x, w[j].x, acc[i][j]);
                acc[i][j] = fmaf(a[i].y, w[j].y, acc[i][j]);
                acc[i][j] = fmaf(a[i].z, w[j].z, acc[i][j]);
                acc[i][j] = fmaf(a[i].w, w[j].w, acc[i][j]);
            }
        }
    }

#pragma unroll
    for (int i = 0; i < 8; i++) {
#pragma unroll
        for (int j = 0; j < CPT; j++) {
            float v = acc[i][j];
            if (ELU) v = (v > 0.0f) ? v : (__expf(v) - 1.0f);
            // consecutive threads (c) write consecutive floats -> conflict-free
            sOut[(r0 + i) * N + c + j * 64] = v;
        }
    }
}

__global__ void __launch_bounds__(NTHREADS, 1)
mlp_quadform_kernel(const float* __restrict__ x,
                    const float* __restrict__ W1, const float* __restrict__ b1,
                    const float* __restrict__ W2, const float* __restrict__ b2,
                    const float* __restrict__ W3, const float* __restrict__ b3,
                    const float* __restrict__ W4, const float* __restrict__ b4,
                    float* __restrict__ out)
{
    extern __shared__ float smem[];
    float* sA = smem;                   // [TB][512]
    float* sB = sA + TB * 512;          // [TB][512]
    float* xs = sB + TB * 512;          // [TB][XSTRIDE]

    const int tid = threadIdx.x;
    const long base = (long)blockIdx.x * TB;

    // Load x tile (coalesced)
#pragma unroll
    for (int idx = tid; idx < TB * 64; idx += NTHREADS) {
        int r = idx >> 6, col = idx & 63;
        xs[r * XSTRIDE + col] = x[(base + r) * 64 + col];
    }
    __syncthreads();

    layer<64,  512, XSTRIDE, true >(xs, sA, W1, b1, tid);   // L1: 64 -> 512, ELU
    __syncthreads();
    layer<512, 512, 512,     true >(sA, sB, W2, b2, tid);   // L2: 512 -> 512, ELU
    __syncthreads();
    layer<512, 256, 512,     true >(sB, sA, W3, b3, tid);   // L3: 512 -> 256, ELU
    __syncthreads();
    layer<256, 64,  256,     false>(sA, sB, W4, b4, tid);   // L4: 256 -> 64, linear
    __syncthreads();

    // value[b] = -(x . z)^2
    if (tid < TB) {
        float s = 0.0f;
#pragma unroll
        for (int k = 0; k < 64; k++)
            s += xs[tid * XSTRIDE + k] * sB[tid * 64 + k];
        out[base + tid] = -s * s;
    }
}

extern "C" void kernel_launch(void* const* d_in, const int* in_sizes, int n_in,
                              void* d_out, int out_size)
{
    const float* x  = (const float*)d_in[0];
    const float* W1 = (const float*)d_in[1];
    const float* b1 = (const float*)d_in[2];
    const float* W2 = (const float*)d_in[3];
    const float* b2 = (const float*)d_in[4];
    const float* W3 = (const float*)d_in[5];
    const float* b3 = (const float*)d_in[6];
    const float* W4 = (const float*)d_in[7];
    const float* b4 = (const float*)d_in[8];
    float* out = (float*)d_out;

    const int batch = in_sizes[0] / 64;          // 65536
    const size_t shmem = SMEM_FLOATS * sizeof(float);   // ~139.8 KB

    cudaFuncSetAttribute(mlp_quadform_kernel,
                         cudaFuncAttributeMaxDynamicSharedMemorySize, (int)shmem);

    dim3 grid(batch / TB);
    mlp_quadform_kernel<<<grid, NTHREADS, shmem>>>(x, W1, b1, W2, b2, W3, b3, W4, b4, out);
}

// round 4
// speedup vs baseline: 5.0520x; 5.0520x over previous
#include <cuda_runtime.h>
#include <cuda_bf16.h>
#include <cstdint>

// value[b] = -( x[b] . MLP(x[b]) )^2  — HMMA (mma.sync bf16) hi/lo split GEMM chain.
// sm_103 baseline target: no tcgen05/TMA; uses ldmatrix + mma.sync + cp.async.

__device__ __nv_bfloat16 g_Whi[442368];
__device__ __nv_bfloat16 g_Wlo[442368];
__device__ uint32_t g_actA[65536UL * 512];
__device__ uint32_t g_actB[65536UL * 512];

__device__ __forceinline__ uint32_t smem_u32(const void* p) {
    uint32_t a;
    asm("{ .reg .u64 t; cvta.to.shared.u64 t, %1; cvt.u32.u64 %0, t; }" : "=r"(a) : "l"(p));
    return a;
}
__device__ __forceinline__ void ldsm4(uint32_t* r, uint32_t addr) {
    asm volatile("ldmatrix.sync.aligned.m8n8.x4.shared.b16 {%0,%1,%2,%3}, [%4];"
        : "=r"(r[0]), "=r"(r[1]), "=r"(r[2]), "=r"(r[3]) : "r"(addr));
}
__device__ __forceinline__ void mma_bf16(float* c, const uint32_t* a, const uint32_t* b) {
    asm volatile("mma.sync.aligned.m16n8k16.row.col.f32.bf16.bf16.f32 "
        "{%0,%1,%2,%3}, {%4,%5,%6,%7}, {%8,%9}, {%0,%1,%2,%3};"
        : "+f"(c[0]), "+f"(c[1]), "+f"(c[2]), "+f"(c[3])
        : "r"(a[0]), "r"(a[1]), "r"(a[2]), "r"(a[3]), "r"(b[0]), "r"(b[1]));
}
#define CP16(dst, src)  asm volatile("cp.async.cg.shared.global [%0], [%1], 16;" :: "r"(dst), "l"(src))
#define CP_COMMIT()     asm volatile("cp.async.commit_group;" ::: "memory")
#define CP_WAIT1()      asm volatile("cp.async.wait_group 1;" ::: "memory")
#define CP_WAIT0()      asm volatile("cp.async.wait_group 0;" ::: "memory")

__device__ __forceinline__ uint32_t pack2(__nv_bfloat16 a, __nv_bfloat16 b) {
    return (uint32_t)__bfloat16_as_ushort(a) | ((uint32_t)__bfloat16_as_ushort(b) << 16);
}
// pack fp32 -> {hi bf16 (low16), lo bf16 (high16)}
__device__ __forceinline__ uint32_t packw(float v) {
    __nv_bfloat16 h = __float2bfloat16(v);
    __nv_bfloat16 l = __float2bfloat16(v - __bfloat162float(h));
    return (uint32_t)__bfloat16_as_ushort(h) | ((uint32_t)__bfloat16_as_ushort(l) << 16);
}

__global__ void split_w(const float* __restrict__ src, int off, int n) {
    int i = blockIdx.x * blockDim.x + threadIdx.x;
    if (i < n) {
        float w = src[i];
        __nv_bfloat16 h = __float2bfloat16(w);
        g_Whi[off + i] = h;
        g_Wlo[off + i] = __float2bfloat16(w - __bfloat162float(h));
    }
}

// =============================================================================
// Layer kernel: Out[b,n] = ELU( A[b,:] . W[n,:] + bias[n] )   (FINAL: fused dot)
// M_CTA = 64 rows; A resident (hi/lo planes); W tiles [NT x 64] double-buffered.
// =============================================================================
template<int K, int N, int NT, bool SRC_F32, bool FINAL>
__global__ void __launch_bounds__(256, 1)
layer_kernel(const void* __restrict__ Asrc, int woff, const float* __restrict__ bias,
             uint32_t* __restrict__ ActOut, const float* __restrict__ x,
             float* __restrict__ outv)
{
    extern __shared__ char sm[];
    constexpr int APLANE  = 64 * K * 2;            // bytes per A plane
    constexpr int WOFF    = 2 * APLANE;
    constexpr int WPLANE  = NT * 128;              // bytes per W plane per buf
    constexpr int WBUF    = 2 * WPLANE;            // hi+lo
    constexpr int BIASOFF = WOFF + 2 * WBUF;
    constexpr int ZOFF    = BIASOFF + N * 4;
    constexpr int KT      = K / 64;
    constexpr int NITER   = (N / NT) * KT;
    constexpr int NTW     = NT / 2;                // cols per warp
    constexpr int JT      = NTW / 8;               // n8 tiles per warp

    const int tid = threadIdx.x, wid = tid >> 5, l = tid & 31;
    const long base = (long)blockIdx.x * 64;
    const uint32_t smb = smem_u32(sm);

    // ---- W tile prefetch (cp.async, swizzled dst) ----
    auto prefetch = [&](int it, int buf) {
        const int nt = it / KT, kt = it % KT;
        const int n0 = nt * NT, k0 = kt * 64;
        #pragma unroll
        for (int i = tid; i < NT * 16; i += 256) {
            const int plane = (i >= NT * 8);
            const int j = plane ? i - NT * 8 : i;
            const int n = j >> 3, c = j & 7;
            const __nv_bfloat16* g = (plane ? g_Wlo : g_Whi) + woff + (long)(n0 + n) * K + k0 + c * 8;
            const uint32_t dst = smb + WOFF + buf * WBUF + plane * WPLANE
                               + n * 128 + ((uint32_t)(c ^ (n & 7)) << 4);
            CP16(dst, g);
        }
    };

    prefetch(0, 0);
    CP_COMMIT();

    // ---- A block resident load: 64 rows x K, split into hi/lo planes ----
    {
        constexpr int V = K / 4;     // vec4 groups per row
        for (int i = tid; i < 64 * V; i += 256) {
            const int r = i / V, k4 = (i % V) * 4;
            const int c = k4 >> 3;
            const int wi = (k4 & 4) << 1;    // byte offset within 16B chunk: 0 or 8
            const uint32_t off = r * (K * 2) + ((uint32_t)(c ^ (r & 7)) << 4) + wi;
            uint32_t hi0, hi1, lo0, lo1;
            if (SRC_F32) {
                const float4 v = ((const float4*)Asrc)[(base + r) * V + (k4 >> 2)];
                __nv_bfloat16 h0 = __float2bfloat16(v.x), h1 = __float2bfloat16(v.y);
                __nv_bfloat16 h2 = __float2bfloat16(v.z), h3 = __float2bfloat16(v.w);
                __nv_bfloat16 e0 = __float2bfloat16(v.x - __bfloat162float(h0));
                __nv_bfloat16 e1 = __float2bfloat16(v.y - __bfloat162float(h1));
                __nv_bfloat16 e2 = __float2bfloat16(v.z - __bfloat162float(h2));
                __nv_bfloat16 e3 = __float2bfloat16(v.w - __bfloat162float(h3));
                hi0 = pack2(h0, h1); hi1 = pack2(h2, h3);
                lo0 = pack2(e0, e1); lo1 = pack2(e2, e3);
            } else {
                const uint4 w = ((const uint4*)Asrc)[(base + r) * V + (k4 >> 2)];
                hi0 = (w.x & 0xFFFFu) | (w.y << 16);
                hi1 = (w.z & 0xFFFFu) | (w.w << 16);
                lo0 = (w.x >> 16) | (w.y & 0xFFFF0000u);
                lo1 = (w.z >> 16) | (w.w & 0xFFFF0000u);
            }
            *(uint32_t*)(sm + off)              = hi0;
            *(uint32_t*)(sm + off + 4)          = hi1;
            *(uint32_t*)(sm + APLANE + off)     = lo0;
            *(uint32_t*)(sm + APLANE + off + 4) = lo1;
        }
        for (int i = tid; i < N; i += 256) *(float*)(sm + BIASOFF + i * 4) = bias[i];
    }

    // ---- per-warp geometry ----
    const int wM = (wid & 3) * 16;          // row block
    const int wN = (wid >> 2) * NTW;        // col block within NT chunk
    const int aRow = wM + (l & 15);
    const uint32_t aRowBase = smb + aRow * (K * 2);
    const uint32_t aSel = (uint32_t)(aRow & 7);
    const int aCk = (l >> 4);               // +0/+1 chunk for ldmatrix halves
    const int bnLoc = (l & 7) | ((l & 16) >> 1);
    const int bcLoc = (l >> 3) & 1;

    float acc[JT * 4];

    for (int nt = 0; nt < N / NT; ++nt) {
        #pragma unroll
        for (int q = 0; q < JT * 4; q++) acc[q] = 0.0f;

        for (int kt = 0; kt < KT; ++kt) {
            const int cur = nt * KT + kt;
            if (cur + 1 < NITER) { prefetch(cur + 1, (cur + 1) & 1); CP_COMMIT(); CP_WAIT1(); }
            else                 { CP_WAIT0(); }
            __syncthreads();
            const uint32_t wb = smb + WOFF + (cur & 1) * WBUF;

            #pragma unroll
            for (int s = 0; s < 4; ++s) {
                const int ck = kt * 8 + s * 2 + aCk;
                const uint32_t aaddr = aRowBase + ((uint32_t)(ck ^ aSel) << 4);
                uint32_t ahi[4], alo[4];
                ldsm4(ahi, aaddr);
                ldsm4(alo, aaddr + APLANE);

                uint32_t bhi[JT][2], blo[JT][2];
                const int bc = s * 2 + bcLoc;
                #pragma unroll
                for (int jj = 0; jj < JT / 2; ++jj) {
                    const int n = wN + 16 * jj + bnLoc;
                    const uint32_t baddr = wb + n * 128 + ((uint32_t)(bc ^ (n & 7)) << 4);
                    uint32_t t[4];
                    ldsm4(t, baddr);
                    bhi[2*jj][0] = t[0]; bhi[2*jj][1] = t[1];
                    bhi[2*jj+1][0] = t[2]; bhi[2*jj+1][1] = t[3];
                    ldsm4(t, baddr + WPLANE);
                    blo[2*jj][0] = t[0]; blo[2*jj][1] = t[1];
                    blo[2*jj+1][0] = t[2]; blo[2*jj+1][1] = t[3];
                }
                #pragma unroll
                for (int j = 0; j < JT; j++) mma_bf16(acc + 4*j, ahi, bhi[j]);
                #pragma unroll
                for (int j = 0; j < JT; j++) mma_bf16(acc + 4*j, ahi, blo[j]);
                #pragma unroll
                for (int j = 0; j < JT; j++) mma_bf16(acc + 4*j, alo, bhi[j]);
            }
            __syncthreads();
        }

        // ---- epilogue for this NT chunk ----
        const int r0 = wM + (l >> 2);
        if (!FINAL) {
            #pragma unroll
            for (int j = 0; j < JT; j++) {
                const int col = nt * NT + wN + j * 8 + (l & 3) * 2;
                const float b0 = *(const float*)(sm + BIASOFF + col * 4);
                const float b1 = *(const float*)(sm + BIASOFF + (col + 1) * 4);
                float v00 = acc[4*j+0] + b0, v01 = acc[4*j+1] + b1;
                float v10 = acc[4*j+2] + b0, v11 = acc[4*j+3] + b1;
                v00 = v00 > 0.f ? v00 : expm1f(v00);
                v01 = v01 > 0.f ? v01 : expm1f(v01);
                v10 = v10 > 0.f ? v10 : expm1f(v10);
                v11 = v11 > 0.f ? v11 : expm1f(v11);
                uint2 w0 = make_uint2(packw(v00), packw(v01));
                uint2 w1 = make_uint2(packw(v10), packw(v11));
                *(uint2*)(ActOut + (base + r0) * N + col)     = w0;
                *(uint2*)(ActOut + (base + r0 + 8) * N + col) = w1;
            }
        } else {
            float* zb = (float*)(sm + ZOFF);
            #pragma unroll
            for (int j = 0; j < JT; j++) {
                const int col = wN + j * 8 + (l & 3) * 2;
                const float b0 = *(const float*)(sm + BIASOFF + col * 4);
                const float b1 = *(const float*)(sm + BIASOFF + (col + 1) * 4);
                zb[r0 * 65 + col]         = acc[4*j+0] + b0;
                zb[r0 * 65 + col + 1]     = acc[4*j+1] + b1;
                zb[(r0 + 8) * 65 + col]     = acc[4*j+2] + b0;
                zb[(r0 + 8) * 65 + col + 1] = acc[4*j+3] + b1;
            }
        }
    }

    if (FINAL) {
        __syncthreads();
        if (tid < 64) {
            const float4* xr = (const float4*)(x + (base + tid) * 64);
            const float* zr = (const float*)(sm + ZOFF) + tid * 65;
            float s = 0.0f;
            #pragma unroll
            for (int q = 0; q < 16; q++) {
                const float4 xv = xr[q];
                s += xv.x * zr[q*4+0] + xv.y * zr[q*4+1]
                   + xv.z * zr[q*4+2] + xv.w * zr[q*4+3];
            }
            outv[base + tid] = -s * s;
        }
    }
}

extern "C" void kernel_launch(void* const* d_in, const int* in_sizes, int n_in,
                              void* d_out, int out_size)
{
    const float* x  = (const float*)d_in[0];
    const float* W1 = (const float*)d_in[1];
    const float* b1 = (const float*)d_in[2];
    const float* W2 = (const float*)d_in[3];
    const float* b2 = (const float*)d_in[4];
    const float* W3 = (const float*)d_in[5];
    const float* b3 = (const float*)d_in[6];
    const float* W4 = (const float*)d_in[7];
    const float* b4 = (const float*)d_in[8];
    float* out = (float*)d_out;

    uint32_t *actA, *actB;
    cudaGetSymbolAddress((void**)&actA, g_actA);
    cudaGetSymbolAddress((void**)&actB, g_actB);

    split_w<<<(32768 + 255) / 256, 256>>>(W1, 0, 32768);
    split_w<<<(262144 + 255) / 256, 256>>>(W2, 32768, 262144);
    split_w<<<(131072 + 255) / 256, 256>>>(W3, 294912, 131072);
    split_w<<<(16384 + 255) / 256, 256>>>(W4, 425984, 16384);

    // smem sizes: 64*K*4 (A hi/lo) + 4*NT*128 (W dbl buf hi/lo) + N*4 (+zbuf)
    constexpr int SZ1 = 64*64*4  + 4*128*128 + 512*4;            // 83968
    constexpr int SZ2 = 64*512*4 + 4*128*128 + 512*4;            // 198656
    constexpr int SZ3 = 64*512*4 + 4*128*128 + 256*4;            // 197632
    constexpr int SZ4 = 64*256*4 + 4*64*128  + 64*4 + 64*65*4;   // 115200

    cudaFuncSetAttribute(layer_kernel<64, 512, 128, true, false>,
                         cudaFuncAttributeMaxDynamicSharedMemorySize, SZ1);
    cudaFuncSetAttribute(layer_kernel<512, 512, 128, false, false>,
                         cudaFuncAttributeMaxDynamicSharedMemorySize, SZ2);
    cudaFuncSetAttribute(layer_kernel<512, 256, 128, false, false>,
                         cudaFuncAttributeMaxDynamicSharedMemorySize, SZ3);
    cudaFuncSetAttribute(layer_kernel<256, 64, 64, false, true>,
                         cudaFuncAttributeMaxDynamicSharedMemorySize, SZ4);

    const int grid = 65536 / 64;   // 1024
    layer_kernel<64, 512, 128, true, false><<<grid, 256, SZ1>>>(x,    0,      b1, actA, nullptr, nullptr);
    layer_kernel<512, 512, 128, false, false><<<grid, 256, SZ2>>>(actA, 32768,  b2, actB, nullptr, nullptr);
    layer_kernel<512, 256, 128, false, false><<<grid, 256, SZ3>>>(actB, 294912, b3, actA, nullptr, nullptr);
    layer_kernel<256, 64, 64, false, true><<<grid, 256, SZ4>>>(actA, 425984, b4, nullptr, x, out);
}

// round 5
// speedup vs baseline: 5.9922x; 1.1861x over previous
#include <cuda_runtime.h>
#include <cuda_bf16.h>
#include <cstdint>

// value[b] = -( x[b] . MLP(x[b]) )^2 — HMMA bf16 hi/lo split GEMM chain.
// M_CTA=128, 512 threads, cp.async double-buffered A+W streams, planar bf16 acts.

__device__ __nv_bfloat16 g_Whi[442368];
__device__ __nv_bfloat16 g_Wlo[442368];
__device__ __nv_bfloat16 g_hiA[65536UL * 512];
__device__ __nv_bfloat16 g_loA[65536UL * 512];
__device__ __nv_bfloat16 g_hiB[65536UL * 512];
__device__ __nv_bfloat16 g_loB[65536UL * 512];

__device__ __forceinline__ uint32_t smem_u32(const void* p) {
    uint32_t a;
    asm("{ .reg .u64 t; cvta.to.shared.u64 t, %1; cvt.u32.u64 %0, t; }" : "=r"(a) : "l"(p));
    return a;
}
__device__ __forceinline__ void ldsm4(uint32_t* r, uint32_t addr) {
    asm volatile("ldmatrix.sync.aligned.m8n8.x4.shared.b16 {%0,%1,%2,%3}, [%4];"
        : "=r"(r[0]), "=r"(r[1]), "=r"(r[2]), "=r"(r[3]) : "r"(addr));
}
__device__ __forceinline__ void mma_bf16(float* c, const uint32_t* a, const uint32_t* b) {
    asm volatile("mma.sync.aligned.m16n8k16.row.col.f32.bf16.bf16.f32 "
        "{%0,%1,%2,%3}, {%4,%5,%6,%7}, {%8,%9}, {%0,%1,%2,%3};"
        : "+f"(c[0]), "+f"(c[1]), "+f"(c[2]), "+f"(c[3])
        : "r"(a[0]), "r"(a[1]), "r"(a[2]), "r"(a[3]), "r"(b[0]), "r"(b[1]));
}
#define CP16(dst, src)  asm volatile("cp.async.cg.shared.global [%0], [%1], 16;" :: "r"(dst), "l"(src))
#define CP_COMMIT()     asm volatile("cp.async.commit_group;" ::: "memory")
#define CP_WAIT1()      asm volatile("cp.async.wait_group 1;" ::: "memory")
#define CP_WAIT0()      asm volatile("cp.async.wait_group 0;" ::: "memory")

__device__ __forceinline__ uint32_t pack2(__nv_bfloat16 a, __nv_bfloat16 b) {
    return (uint32_t)__bfloat16_as_ushort(a) | ((uint32_t)__bfloat16_as_ushort(b) << 16);
}
__device__ __forceinline__ void split1(float v, __nv_bfloat16& h, __nv_bfloat16& l) {
    h = __float2bfloat16(v);
    l = __float2bfloat16(v - __bfloat162float(h));
}

__global__ void split_all(const float* __restrict__ W1, const float* __restrict__ W2,
                          const float* __restrict__ W3, const float* __restrict__ W4) {
    int i = blockIdx.x * blockDim.x + threadIdx.x;
    if (i >= 442368) return;
    float w;
    if (i < 32768)       w = W1[i];
    else if (i < 294912) w = W2[i - 32768];
    else if (i < 425984) w = W3[i - 294912];
    else                 w = W4[i - 425984];
    __nv_bfloat16 h, l; split1(w, h, l);
    g_Whi[i] = h; g_Wlo[i] = l;
}

// ============================ Layer 1: x(f32,K=64) -> 512, ELU ============================
// A resident (hi/lo, 32KB), W1 resident (128KB). 16 warps: 8M x 2N, nt loop x4 (NT=128).
__global__ void __launch_bounds__(512, 1)
l1_kernel(const float* __restrict__ x, const float* __restrict__ bias,
          __nv_bfloat16* __restrict__ outHi, __nv_bfloat16* __restrict__ outLo)
{
    extern __shared__ char sm[];
    // [0,16384) A_hi | [16384,32768) A_lo | [32768,98304) W_hi | [98304,163840) W_lo | bias
    const int tid = threadIdx.x, wid = tid >> 5, l = tid & 31;
    const long base = (long)blockIdx.x * 128;
    const uint32_t smb = smem_u32(sm);

    // W1 resident via cp.async: 512 rows x 8 chunks x 2 planes
    #pragma unroll
    for (int i = tid; i < 8192; i += 512) {
        const int plane = i >> 12, j = i & 4095;
        const int n = j >> 3, c = j & 7;
        const __nv_bfloat16* src = (plane ? g_Wlo : g_Whi) + n * 64 + c * 8;
        CP16(smb + 32768 + plane * 65536 + n * 128 + ((uint32_t)(c ^ (n & 7)) << 4), src);
    }
    CP_COMMIT();

    // A: convert fp32 x -> hi/lo planes (swizzled)
    #pragma unroll
    for (int i = tid; i < 2048; i += 512) {
        const int r = i >> 4, k4 = (i & 15) * 4;
        const int c = k4 >> 3, wi = (k4 & 4) << 1;
        const float4 v = *(const float4*)(x + (base + r) * 64 + k4);
        __nv_bfloat16 h0, h1, h2, h3, e0, e1, e2, e3;
        split1(v.x, h0, e0); split1(v.y, h1, e1); split1(v.z, h2, e2); split1(v.w, h3, e3);
        const uint32_t off = r * 128 + ((uint32_t)(c ^ (r & 7)) << 4) + wi;
        *(uint32_t*)(sm + off)             = pack2(h0, h1);
        *(uint32_t*)(sm + off + 4)         = pack2(h2, h3);
        *(uint32_t*)(sm + 16384 + off)     = pack2(e0, e1);
        *(uint32_t*)(sm + 16384 + off + 4) = pack2(e2, e3);
    }
    for (int i = tid; i < 512; i += 512) *(float*)(sm + 163840 + i * 4) = bias[i];
    CP_WAIT0();
    __syncthreads();

    const int wM = (wid & 7) * 16, wN = (wid >> 3) * 64;
    const int aRow = wM + (l & 15), aCk = l >> 4;
    const uint32_t aSel = (uint32_t)(aRow & 7);
    const int bnLoc = (l & 7) | ((l & 16) >> 1), bcLoc = (l >> 3) & 1;
    const uint32_t aRowBase = smb + aRow * 128;

    #pragma unroll 1
    for (int nt = 0; nt < 4; nt++) {
        float acc[32];
        #pragma unroll
        for (int q = 0; q < 32; q++) acc[q] = 0.0f;
        #pragma unroll
        for (int s = 0; s < 4; s++) {
            const int ck = s * 2 + aCk;
            uint32_t ahi[4], alo[4];
            const uint32_t aaddr = aRowBase + ((uint32_t)(ck ^ aSel) << 4);
            ldsm4(ahi, aaddr); ldsm4(alo, aaddr + 16384);
            const int bc = s * 2 + bcLoc;
            #pragma unroll
            for (int g = 0; g < 2; g++) {
                uint32_t bh[4][2], bl[4][2], t[4];
                #pragma unroll
                for (int pp = 0; pp < 2; pp++) {
                    const int n = nt * 128 + wN + 16 * (2 * g + pp) + bnLoc;
                    const uint32_t ba = smb + 32768 + n * 128 + ((uint32_t)(bc ^ (n & 7)) << 4);
                    ldsm4(t, ba);
                    bh[2*pp][0]=t[0]; bh[2*pp][1]=t[1]; bh[2*pp+1][0]=t[2]; bh[2*pp+1][1]=t[3];
                    ldsm4(t, ba + 65536);
                    bl[2*pp][0]=t[0]; bl[2*pp][1]=t[1]; bl[2*pp+1][0]=t[2]; bl[2*pp+1][1]=t[3];
                }
                #pragma unroll
                for (int u = 0; u < 4; u++) mma_bf16(acc + 4*(4*g+u), ahi, bh[u]);
                #pragma unroll
                for (int u = 0; u < 4; u++) mma_bf16(acc + 4*(4*g+u), ahi, bl[u]);
                #pragma unroll
                for (int u = 0; u < 4; u++) mma_bf16(acc + 4*(4*g+u), alo, bh[u]);
            }
        }
        // epilogue: ELU + split + planar store
        const int r0 = wM + (l >> 2);
        #pragma unroll
        for (int j = 0; j < 8; j++) {
            const int col = nt * 128 + wN + j * 8 + (l & 3) * 2;
            const float b0 = *(const float*)(sm + 163840 + col * 4);
            const float b1 = *(const float*)(sm + 163840 + col * 4 + 4);
            float v00 = acc[4*j+0] + b0, v01 = acc[4*j+1] + b1;
            float v10 = acc[4*j+2] + b0, v11 = acc[4*j+3] + b1;
            v00 = v00 > 0.f ? v00 : expm1f(v00);
            v01 = v01 > 0.f ? v01 : expm1f(v01);
            v10 = v10 > 0.f ? v10 : expm1f(v10);
            v11 = v11 > 0.f ? v11 : expm1f(v11);
            __nv_bfloat16 h0,h1,h2,h3,e0,e1,e2,e3;
            split1(v00,h0,e0); split1(v01,h1,e1); split1(v10,h2,e2); split1(v11,h3,e3);
            *(uint32_t*)(outHi + (base + r0) * 512 + col)     = pack2(h0, h1);
            *(uint32_t*)(outLo + (base + r0) * 512 + col)     = pack2(e0, e1);
            *(uint32_t*)(outHi + (base + r0 + 8) * 512 + col) = pack2(h2, h3);
            *(uint32_t*)(outLo + (base + r0 + 8) * 512 + col) = pack2(e2, e3);
        }
    }
}

// ============================ Mid layers: K=512 -> N (ELU) ============================
// A and W streamed in 64-wide k-tiles, double buffered. NT=256, 16 warps 8Mx2N, JT=16.
template<int N>
__global__ void __launch_bounds__(512, 1)
mid_kernel(const __nv_bfloat16* __restrict__ inHi, const __nv_bfloat16* __restrict__ inLo,
           int woff, const float* __restrict__ bias,
           __nv_bfloat16* __restrict__ outHi, __nv_bfloat16* __restrict__ outLo)
{
    extern __shared__ char sm[];
    constexpr int K = 512, NT = 256, KT = 8, NPASS = N / NT, NITER = NPASS * KT;
    constexpr int ASZ = 32768;                 // per buf: hi 16K + lo 16K
    constexpr int WOFFS = 2 * ASZ;             // 65536
    constexpr int WSZ = NT * 256;              // 65536 per buf (hi 32K + lo 32K)
    constexpr int BIASOFF = WOFFS + 2 * WSZ;   // 196608

    const int tid = threadIdx.x, wid = tid >> 5, l = tid & 31;
    const long base = (long)blockIdx.x * 128;
    const uint32_t smb = smem_u32(sm);

    auto prefetch = [&](int it, int buf) {
        const int nt = it / KT, kt = it % KT;
        const int k0 = kt * 64, n0 = nt * NT;
        #pragma unroll
        for (int i = tid; i < 2048; i += 512) {          // A: 128 rows x 8 x 2 planes
            const int plane = i >> 10, j = i & 1023;
            const int r = j >> 3, c = j & 7;
            const __nv_bfloat16* src = (plane ? inLo : inHi) + (base + r) * K + k0 + c * 8;
            CP16(smb + buf * ASZ + plane * 16384 + r * 128 + ((uint32_t)(c ^ (r & 7)) << 4), src);
        }
        #pragma unroll
        for (int i = tid; i < 4096; i += 512) {          // W: 256 rows x 8 x 2 planes
            const int plane = i >> 11, j = i & 2047;
            const int n = j >> 3, c = j & 7;
            const __nv_bfloat16* src = (plane ? g_Wlo : g_Whi) + woff + (long)(n0 + n) * K + k0 + c * 8;
            CP16(smb + WOFFS + buf * WSZ + plane * 32768 + n * 128 + ((uint32_t)(c ^ (n & 7)) << 4), src);
        }
    };

    prefetch(0, 0); CP_COMMIT();
    for (int i = tid; i < N; i += 512) *(float*)(sm + BIASOFF + i * 4) = bias[i];

    const int wM = (wid & 7) * 16, wN = (wid >> 3) * 128;
    const int aRow = wM + (l & 15), aCk = l >> 4;
    const uint32_t aSel = (uint32_t)(aRow & 7);
    const int bnLoc = (l & 7) | ((l & 16) >> 1), bcLoc = (l >> 3) & 1;

    float acc[64];

    #pragma unroll 1
    for (int it = 0; it < NITER; ++it) {
        const int nt = it / KT, kt = it % KT;
        if (it + 1 < NITER) { prefetch(it + 1, (it + 1) & 1); CP_COMMIT(); CP_WAIT1(); }
        else                 CP_WAIT0();
        __syncthreads();
        if (kt == 0) {
            #pragma unroll
            for (int q = 0; q < 64; q++) acc[q] = 0.0f;
        }
        const uint32_t ab = smb + (it & 1) * ASZ;
        const uint32_t wb = smb + WOFFS + (it & 1) * WSZ;
        #pragma unroll
        for (int s = 0; s < 4; s++) {
            const int ck = s * 2 + aCk;
            uint32_t ahi[4], alo[4];
            const uint32_t aaddr = ab + aRow * 128 + ((uint32_t)(ck ^ aSel) << 4);
            ldsm4(ahi, aaddr); ldsm4(alo, aaddr + 16384);
            const int bc = s * 2 + bcLoc;
            #pragma unroll
            for (int g = 0; g < 4; g++) {
                uint32_t bh[4][2], bl[4][2], t[4];
                #pragma unroll
                for (int pp = 0; pp < 2; pp++) {
                    const int n = wN + 16 * (2 * g + pp) + bnLoc;
                    const uint32_t ba = wb + n * 128 + ((uint32_t)(bc ^ (n & 7)) << 4);
                    ldsm4(t, ba);
                    bh[2*pp][0]=t[0]; bh[2*pp][1]=t[1]; bh[2*pp+1][0]=t[2]; bh[2*pp+1][1]=t[3];
                    ldsm4(t, ba + 32768);
                    bl[2*pp][0]=t[0]; bl[2*pp][1]=t[1]; bl[2*pp+1][0]=t[2]; bl[2*pp+1][1]=t[3];
                }
                #pragma unroll
                for (int u = 0; u < 4; u++) mma_bf16(acc + 4*(4*g+u), ahi, bh[u]);
                #pragma unroll
                for (int u = 0; u < 4; u++) mma_bf16(acc + 4*(4*g+u), ahi, bl[u]);
                #pragma unroll
                for (int u = 0; u < 4; u++) mma_bf16(acc + 4*(4*g+u), alo, bh[u]);
            }
        }
        if (kt == KT - 1) {
            const int r0 = wM + (l >> 2);
            #pragma unroll
            for (int j = 0; j < 16; j++) {
                const int col = nt * NT + wN + j * 8 + (l & 3) * 2;
                const float b0 = *(const float*)(sm + BIASOFF + col * 4);
                const float b1 = *(const float*)(sm + BIASOFF + col * 4 + 4);
                float v00 = acc[4*j+0] + b0, v01 = acc[4*j+1] + b1;
                float v10 = acc[4*j+2] + b0, v11 = acc[4*j+3] + b1;
                v00 = v00 > 0.f ? v00 : expm1f(v00);
                v01 = v01 > 0.f ? v01 : expm1f(v01);
                v10 = v10 > 0.f ? v10 : expm1f(v10);
                v11 = v11 > 0.f ? v11 : expm1f(v11);
                __nv_bfloat16 h0,h1,h2,h3,e0,e1,e2,e3;
                split1(v00,h0,e0); split1(v01,h1,e1); split1(v10,h2,e2); split1(v11,h3,e3);
                *(uint32_t*)(outHi + (base + r0) * N + col)     = pack2(h0, h1);
                *(uint32_t*)(outLo + (base + r0) * N + col)     = pack2(e0, e1);
                *(uint32_t*)(outHi + (base + r0 + 8) * N + col) = pack2(h2, h3);
                *(uint32_t*)(outLo + (base + r0 + 8) * N + col) = pack2(e2, e3);
            }
        }
        __syncthreads();
    }
}

// ============================ Layer 4 + fused dot: K=256 -> 64, out=-(x.z)^2 ============================
__global__ void __launch_bounds__(512, 1)
l4_kernel(const __nv_bfloat16* __restrict__ inHi, const __nv_bfloat16* __restrict__ inLo,
          const float* __restrict__ bias, const float* __restrict__ x, float* __restrict__ outv)
{
    extern __shared__ char sm[];
    // [0,65536) A dblbuf | [65536,131072) W4 resident (row stride 512B) | [131072,131328) bias | z
    constexpr int K = 256, KT = 4, ZOFF = 131328;
    const int tid = threadIdx.x, wid = tid >> 5, l = tid & 31;
    const long base = (long)blockIdx.x * 128;
    const uint32_t smb = smem_u32(sm);

    auto prefA = [&](int kt, int buf) {
        const int k0 = kt * 64;
        #pragma unroll
        for (int i = tid; i < 2048; i += 512) {
            const int plane = i >> 10, j = i & 1023;
            const int r = j >> 3, c = j & 7;
            const __nv_bfloat16* src = (plane ? inLo : inHi) + (base + r) * K + k0 + c * 8;
            CP16(smb + buf * 32768 + plane * 16384 + r * 128 + ((uint32_t)(c ^ (r & 7)) << 4), src);
        }
    };

    // W4 resident: 64 rows x 32 chunks x 2 planes (row stride 512B)
    #pragma unroll
    for (int i = tid; i < 4096; i += 512) {
        const int plane = i >> 11, j = i & 2047;
        const int n = j >> 5, c = j & 31;
        const __nv_bfloat16* src = (plane ? g_Wlo : g_Whi) + 425984 + n * 256 + c * 8;
        CP16(smb + 65536 + plane * 32768 + n * 512 + (((uint32_t)(c ^ (n & 7))) << 4), src);
    }
    prefA(0, 0); CP_COMMIT();
    if (tid < 64) *(float*)(sm + 131072 + tid * 4) = bias[tid];

    const int wM = (wid & 7) * 16, wN = (wid >> 3) * 32;
    const int aRow = wM + (l & 15), aCk = l >> 4;
    const uint32_t aSel = (uint32_t)(aRow & 7);
    const int bnLoc = (l & 7) | ((l & 16) >> 1), bcLoc = (l >> 3) & 1;

    float acc[16];
    #pragma unroll
    for (int q = 0; q < 16; q++) acc[q] = 0.0f;

    #pragma unroll 1
    for (int kt = 0; kt < KT; ++kt) {
        if (kt + 1 < KT) { prefA(kt + 1, (kt + 1) & 1); CP_COMMIT(); CP_WAIT1(); }
        else              CP_WAIT0();
        __syncthreads();
        const uint32_t ab = smb + (kt & 1) * 32768;
        #pragma unroll
        for (int s = 0; s < 4; s++) {
            const int ck = s * 2 + aCk;
            uint32_t ahi[4], alo[4];
            const uint32_t aaddr = ab + aRow * 128 + ((uint32_t)(ck ^ aSel) << 4);
            ldsm4(ahi, aaddr); ldsm4(alo, aaddr + 16384);
            const int bck = kt * 8 + s * 2 + bcLoc;
            uint32_t bh[4][2], bl[4][2], t[4];
            #pragma unroll
            for (int pp = 0; pp < 2; pp++) {
                const int n = wN + 16 * pp + bnLoc;
                const uint32_t ba = smb + 65536 + n * 512 + ((uint32_t)(bck ^ (n & 7)) << 4);
                ldsm4(t, ba);
                bh[2*pp][0]=t[0]; bh[2*pp][1]=t[1]; bh[2*pp+1][0]=t[2]; bh[2*pp+1][1]=t[3];
                ldsm4(t, ba + 32768);
                bl[2*pp][0]=t[0]; bl[2*pp][1]=t[1]; bl[2*pp+1][0]=t[2]; bl[2*pp+1][1]=t[3];
            }
            #pragma unroll
            for (int u = 0; u < 4; u++) mma_bf16(acc + 4*u, ahi, bh[u]);
            #pragma unroll
            for (int u = 0; u < 4; u++) mma_bf16(acc + 4*u, ahi, bl[u]);
            #pragma unroll
            for (int u = 0; u < 4; u++) mma_bf16(acc + 4*u, alo, bh[u]);
        }
        __syncthreads();
    }

    // z -> smem, then fused dot
    float* zb = (float*)(sm + ZOFF);
    const int r0 = wM + (l >> 2);
    #pragma unroll
    for (int j = 0; j < 4; j++) {
        const int col = wN + j * 8 + (l & 3) * 2;
        const float b0 = *(const float*)(sm + 131072 + col * 4);
        const float b1 = *(const float*)(sm + 131072 + col * 4 + 4);
        zb[r0 * 66 + col]           = acc[4*j+0] + b0;
        zb[r0 * 66 + col + 1]       = acc[4*j+1] + b1;
        zb[(r0 + 8) * 66 + col]     = acc[4*j+2] + b0;
        zb[(r0 + 8) * 66 + col + 1] = acc[4*j+3] + b1;
    }
    __syncthreads();
    if (tid < 128) {
        const float4* xr = (const float4*)(x + (base + tid) * 64);
        const float* zr = zb + tid * 66;
        float s = 0.0f;
        #pragma unroll
        for (int q = 0; q < 16; q++) {
            const float4 xv = xr[q];
            s += xv.x * zr[q*4+0] + xv.y * zr[q*4+1] + xv.z * zr[q*4+2] + xv.w * zr[q*4+3];
        }
        outv[base + tid] = -s * s;
    }
}

extern "C" void kernel_launch(void* const* d_in, const int* in_sizes, int n_in,
                              void* d_out, int out_size)
{
    const float* x  = (const float*)d_in[0];
    const float* W1 = (const float*)d_in[1];
    const float* b1 = (const float*)d_in[2];
    const float* W2 = (const float*)d_in[3];
    const float* b2 = (const float*)d_in[4];
    const float* W3 = (const float*)d_in[5];
    const float* b3 = (const float*)d_in[6];
    const float* W4 = (const float*)d_in[7];
    const float* b4 = (const float*)d_in[8];
    float* out = (float*)d_out;

    __nv_bfloat16 *hiA, *loA, *hiB, *loB;
    cudaGetSymbolAddress((void**)&hiA, g_hiA);
    cudaGetSymbolAddress((void**)&loA, g_loA);
    cudaGetSymbolAddress((void**)&hiB, g_hiB);
    cudaGetSymbolAddress((void**)&loB, g_loB);

    split_all<<<(442368 + 511) / 512, 512>>>(W1, W2, W3, W4);

    constexpr int SZ1 = 165888;   // 32K A + 128K W + 2K bias
    constexpr int SZM = 198656;   // 64K A dbl + 128K W dbl + 2K bias
    constexpr int SZ4 = 165120;   // 64K A dbl + 64K W + 256B bias + 33K z
    cudaFuncSetAttribute(l1_kernel,      cudaFuncAttributeMaxDynamicSharedMemorySize, SZ1);
    cudaFuncSetAttribute(mid_kernel<512>, cudaFuncAttributeMaxDynamicSharedMemorySize, SZM);
    cudaFuncSetAttribute(mid_kernel<256>, cudaFuncAttributeMaxDynamicSharedMemorySize, SZM);
    cudaFuncSetAttribute(l4_kernel,      cudaFuncAttributeMaxDynamicSharedMemorySize, SZ4);

    const int grid = 65536 / 128;  // 512
    l1_kernel<<<grid, 512, SZ1>>>(x, b1, hiA, loA);
    mid_kernel<512><<<grid, 512, SZM>>>(hiA, loA, 32768,  b2, hiB, loB);
    mid_kernel<256><<<grid, 512, SZM>>>(hiB, loB, 294912, b3, hiA, loA);
    l4_kernel<<<grid, 512, SZ4>>>(hiA, loA, b4, x, out);
}

// round 6
// speedup vs baseline: 5.9989x; 1.0011x over previous
#include <cuda_runtime.h>
#include <cuda_bf16.h>
#include <cstdint>

// value[b] = -( x[b] . MLP(x[b]) )^2 — HMMA bf16 hi/lo split GEMM chain.
// M_CTA=128, 512 threads, cp.async double-buffered A+W streams, planar bf16 acts.
// R6: mid kernels use 4Mx4N warp layout (M=32/warp) -> 33% less LDSM per MMA.

__device__ __nv_bfloat16 g_Whi[442368];
__device__ __nv_bfloat16 g_Wlo[442368];
__device__ __nv_bfloat16 g_hiA[65536UL * 512];
__device__ __nv_bfloat16 g_loA[65536UL * 512];
__device__ __nv_bfloat16 g_hiB[65536UL * 512];
__device__ __nv_bfloat16 g_loB[65536UL * 512];

__device__ __forceinline__ uint32_t smem_u32(const void* p) {
    uint32_t a;
    asm("{ .reg .u64 t; cvta.to.shared.u64 t, %1; cvt.u32.u64 %0, t; }" : "=r"(a) : "l"(p));
    return a;
}
__device__ __forceinline__ void ldsm4(uint32_t* r, uint32_t addr) {
    asm volatile("ldmatrix.sync.aligned.m8n8.x4.shared.b16 {%0,%1,%2,%3}, [%4];"
        : "=r"(r[0]), "=r"(r[1]), "=r"(r[2]), "=r"(r[3]) : "r"(addr));
}
__device__ __forceinline__ void mma_bf16(float* c, const uint32_t* a, const uint32_t* b) {
    asm volatile("mma.sync.aligned.m16n8k16.row.col.f32.bf16.bf16.f32 "
        "{%0,%1,%2,%3}, {%4,%5,%6,%7}, {%8,%9}, {%0,%1,%2,%3};"
        : "+f"(c[0]), "+f"(c[1]), "+f"(c[2]), "+f"(c[3])
        : "r"(a[0]), "r"(a[1]), "r"(a[2]), "r"(a[3]), "r"(b[0]), "r"(b[1]));
}
#define CP16(dst, src)  asm volatile("cp.async.cg.shared.global [%0], [%1], 16;" :: "r"(dst), "l"(src))
#define CP_COMMIT()     asm volatile("cp.async.commit_group;" ::: "memory")
#define CP_WAIT1()      asm volatile("cp.async.wait_group 1;" ::: "memory")
#define CP_WAIT0()      asm volatile("cp.async.wait_group 0;" ::: "memory")

__device__ __forceinline__ uint32_t pack2(__nv_bfloat16 a, __nv_bfloat16 b) {
    return (uint32_t)__bfloat16_as_ushort(a) | ((uint32_t)__bfloat16_as_ushort(b) << 16);
}
__device__ __forceinline__ void split1(float v, __nv_bfloat16& h, __nv_bfloat16& l) {
    h = __float2bfloat16(v);
    l = __float2bfloat16(v - __bfloat162float(h));
}

__global__ void split_all(const float* __restrict__ W1, const float* __restrict__ W2,
                          const float* __restrict__ W3, const float* __restrict__ W4) {
    int i = blockIdx.x * blockDim.x + threadIdx.x;
    if (i >= 442368) return;
    float w;
    if (i < 32768)       w = W1[i];
    else if (i < 294912) w = W2[i - 32768];
    else if (i < 425984) w = W3[i - 294912];
    else                 w = W4[i - 425984];
    __nv_bfloat16 h, l; split1(w, h, l);
    g_Whi[i] = h; g_Wlo[i] = l;
}

// ============================ Layer 1: x(f32,K=64) -> 512, ELU ============================
__global__ void __launch_bounds__(512, 1)
l1_kernel(const float* __restrict__ x, const float* __restrict__ bias,
          __nv_bfloat16* __restrict__ outHi, __nv_bfloat16* __restrict__ outLo)
{
    extern __shared__ char sm[];
    const int tid = threadIdx.x, wid = tid >> 5, l = tid & 31;
    const long base = (long)blockIdx.x * 128;
    const uint32_t smb = smem_u32(sm);

    #pragma unroll
    for (int i = tid; i < 8192; i += 512) {
        const int plane = i >> 12, j = i & 4095;
        const int n = j >> 3, c = j & 7;
        const __nv_bfloat16* src = (plane ? g_Wlo : g_Whi) + n * 64 + c * 8;
        CP16(smb + 32768 + plane * 65536 + n * 128 + ((uint32_t)(c ^ (n & 7)) << 4), src);
    }
    CP_COMMIT();

    #pragma unroll
    for (int i = tid; i < 2048; i += 512) {
        const int r = i >> 4, k4 = (i & 15) * 4;
        const int c = k4 >> 3, wi = (k4 & 4) << 1;
        const float4 v = *(const float4*)(x + (base + r) * 64 + k4);
        __nv_bfloat16 h0, h1, h2, h3, e0, e1, e2, e3;
        split1(v.x, h0, e0); split1(v.y, h1, e1); split1(v.z, h2, e2); split1(v.w, h3, e3);
        const uint32_t off = r * 128 + ((uint32_t)(c ^ (r & 7)) << 4) + wi;
        *(uint32_t*)(sm + off)             = pack2(h0, h1);
        *(uint32_t*)(sm + off + 4)         = pack2(h2, h3);
        *(uint32_t*)(sm + 16384 + off)     = pack2(e0, e1);
        *(uint32_t*)(sm + 16384 + off + 4) = pack2(e2, e3);
    }
    for (int i = tid; i < 512; i += 512) *(float*)(sm + 163840 + i * 4) = bias[i];
    CP_WAIT0();
    __syncthreads();

    const int wM = (wid & 7) * 16, wN = (wid >> 3) * 64;
    const int aRow = wM + (l & 15), aCk = l >> 4;
    const uint32_t aSel = (uint32_t)(aRow & 7);
    const int bnLoc = (l & 7) | ((l & 16) >> 1), bcLoc = (l >> 3) & 1;
    const uint32_t aRowBase = smb + aRow * 128;

    #pragma unroll 1
    for (int nt = 0; nt < 4; nt++) {
        float acc[32];
        #pragma unroll
        for (int q = 0; q < 32; q++) acc[q] = 0.0f;
        #pragma unroll
        for (int s = 0; s < 4; s++) {
            const int ck = s * 2 + aCk;
            uint32_t ahi[4], alo[4];
            const uint32_t aaddr = aRowBase + ((uint32_t)(ck ^ aSel) << 4);
            ldsm4(ahi, aaddr); ldsm4(alo, aaddr + 16384);
            const int bc = s * 2 + bcLoc;
            #pragma unroll
            for (int g = 0; g < 2; g++) {
                uint32_t bh[4][2], bl[4][2], t[4];
                #pragma unroll
                for (int pp = 0; pp < 2; pp++) {
                    const int n = nt * 128 + wN + 16 * (2 * g + pp) + bnLoc;
                    const uint32_t ba = smb + 32768 + n * 128 + ((uint32_t)(bc ^ (n & 7)) << 4);
                    ldsm4(t, ba);
                    bh[2*pp][0]=t[0]; bh[2*pp][1]=t[1]; bh[2*pp+1][0]=t[2]; bh[2*pp+1][1]=t[3];
                    ldsm4(t, ba + 65536);
                    bl[2*pp][0]=t[0]; bl[2*pp][1]=t[1]; bl[2*pp+1][0]=t[2]; bl[2*pp+1][1]=t[3];
                }
                #pragma unroll
                for (int u = 0; u < 4; u++) mma_bf16(acc + 4*(4*g+u), ahi, bh[u]);
                #pragma unroll
                for (int u = 0; u < 4; u++) mma_bf16(acc + 4*(4*g+u), ahi, bl[u]);
                #pragma unroll
                for (int u = 0; u < 4; u++) mma_bf16(acc + 4*(4*g+u), alo, bh[u]);
            }
        }
        const int r0 = wM + (l >> 2);
        #pragma unroll
        for (int j = 0; j < 8; j++) {
            const int col = nt * 128 + wN + j * 8 + (l & 3) * 2;
            const float b0 = *(const float*)(sm + 163840 + col * 4);
            const float b1 = *(const float*)(sm + 163840 + col * 4 + 4);
            float v00 = acc[4*j+0] + b0, v01 = acc[4*j+1] + b1;
            float v10 = acc[4*j+2] + b0, v11 = acc[4*j+3] + b1;
            v00 = v00 > 0.f ? v00 : expm1f(v00);
            v01 = v01 > 0.f ? v01 : expm1f(v01);
            v10 = v10 > 0.f ? v10 : expm1f(v10);
            v11 = v11 > 0.f ? v11 : expm1f(v11);
            __nv_bfloat16 h0,h1,h2,h3,e0,e1,e2,e3;
            split1(v00,h0,e0); split1(v01,h1,e1); split1(v10,h2,e2); split1(v11,h3,e3);
            *(uint32_t*)(outHi + (base + r0) * 512 + col)     = pack2(h0, h1);
            *(uint32_t*)(outLo + (base + r0) * 512 + col)     = pack2(e0, e1);
            *(uint32_t*)(outHi + (base + r0 + 8) * 512 + col) = pack2(h2, h3);
            *(uint32_t*)(outLo + (base + r0 + 8) * 512 + col) = pack2(e2, e3);
        }
    }
}

// ============================ Mid layers: K=512 -> N (ELU), 4Mx4N warps ============================
template<int N>
__global__ void __launch_bounds__(512, 1)
mid_kernel(const __nv_bfloat16* __restrict__ inHi, const __nv_bfloat16* __restrict__ inLo,
           int woff, const float* __restrict__ bias,
           __nv_bfloat16* __restrict__ outHi, __nv_bfloat16* __restrict__ outLo)
{
    extern __shared__ char sm[];
    constexpr int K = 512, NT = 256, KT = 8, NPASS = N / NT, NITER = NPASS * KT;
    constexpr int ASZ = 32768;
    constexpr int WOFFS = 2 * ASZ;
    constexpr int WSZ = NT * 256;
    constexpr int BIASOFF = WOFFS + 2 * WSZ;

    const int tid = threadIdx.x, wid = tid >> 5, l = tid & 31;
    const long base = (long)blockIdx.x * 128;
    const uint32_t smb = smem_u32(sm);

    auto prefetch = [&](int it, int buf) {
        const int nt = it / KT, kt = it % KT;
        const int k0 = kt * 64, n0 = nt * NT;
        #pragma unroll
        for (int i = tid; i < 2048; i += 512) {
            const int plane = i >> 10, j = i & 1023;
            const int r = j >> 3, c = j & 7;
            const __nv_bfloat16* src = (plane ? inLo : inHi) + (base + r) * K + k0 + c * 8;
            CP16(smb + buf * ASZ + plane * 16384 + r * 128 + ((uint32_t)(c ^ (r & 7)) << 4), src);
        }
        #pragma unroll
        for (int i = tid; i < 4096; i += 512) {
            const int plane = i >> 11, j = i & 2047;
            const int n = j >> 3, c = j & 7;
            const __nv_bfloat16* src = (plane ? g_Wlo : g_Whi) + woff + (long)(n0 + n) * K + k0 + c * 8;
            CP16(smb + WOFFS + buf * WSZ + plane * 32768 + n * 128 + ((uint32_t)(c ^ (n & 7)) << 4), src);
        }
    };

    prefetch(0, 0); CP_COMMIT();
    for (int i = tid; i < N; i += 512) *(float*)(sm + BIASOFF + i * 4) = bias[i];

    // 4M x 4N: warp M=32 (two m16 tiles), warp N=64 (8 n8 tiles)
    const int wM = (wid & 3) * 32, wN = (wid >> 2) * 64;
    const int aRow = wM + (l & 15), aCk = l >> 4;
    const uint32_t aSel = (uint32_t)(aRow & 7);
    const int bnLoc = (l & 7) | ((l & 16) >> 1), bcLoc = (l >> 3) & 1;

    float acc[64];   // [mt][jt][4] = mt*32 + jt*4

    #pragma unroll 1
    for (int it = 0; it < NITER; ++it) {
        const int nt = it / KT, kt = it % KT;
        if (it + 1 < NITER) { prefetch(it + 1, (it + 1) & 1); CP_COMMIT(); CP_WAIT1(); }
        else                 CP_WAIT0();
        __syncthreads();
        if (kt == 0) {
            #pragma unroll
            for (int q = 0; q < 64; q++) acc[q] = 0.0f;
        }
        const uint32_t ab = smb + (it & 1) * ASZ;
        const uint32_t wb = smb + WOFFS + (it & 1) * WSZ;
        #pragma unroll
        for (int s = 0; s < 4; s++) {
            const int ck = s * 2 + aCk;
            uint32_t ahi[2][4], alo[2][4];
            #pragma unroll
            for (int mt = 0; mt < 2; mt++) {
                const uint32_t aaddr = ab + (aRow + mt * 16) * 128 + ((uint32_t)(ck ^ aSel) << 4);
                ldsm4(ahi[mt], aaddr); ldsm4(alo[mt], aaddr + 16384);
            }
            const int bc = s * 2 + bcLoc;
            #pragma unroll
            for (int g = 0; g < 2; g++) {
                uint32_t bh[4][2], bl[4][2], t[4];
                #pragma unroll
                for (int pp = 0; pp < 2; pp++) {
                    const int n = wN + g * 32 + 16 * pp + bnLoc;
                    const uint32_t ba = wb + n * 128 + ((uint32_t)(bc ^ (n & 7)) << 4);
                    ldsm4(t, ba);
                    bh[2*pp][0]=t[0]; bh[2*pp][1]=t[1]; bh[2*pp+1][0]=t[2]; bh[2*pp+1][1]=t[3];
                    ldsm4(t, ba + 32768);
                    bl[2*pp][0]=t[0]; bl[2*pp][1]=t[1]; bl[2*pp+1][0]=t[2]; bl[2*pp+1][1]=t[3];
                }
                #pragma unroll
                for (int mt = 0; mt < 2; mt++) {
                    float* am = acc + mt * 32 + g * 16;
                    #pragma unroll
                    for (int u = 0; u < 4; u++) mma_bf16(am + 4*u, ahi[mt], bh[u]);
                    #pragma unroll
                    for (int u = 0; u < 4; u++) mma_bf16(am + 4*u, ahi[mt], bl[u]);
                    #pragma unroll
                    for (int u = 0; u < 4; u++) mma_bf16(am + 4*u, alo[mt], bh[u]);
                }
            }
        }
        if (kt == KT - 1) {
            #pragma unroll
            for (int mt = 0; mt < 2; mt++) {
                const int r0 = wM + mt * 16 + (l >> 2);
                #pragma unroll
                for (int j = 0; j < 8; j++) {
                    const int col = nt * NT + wN + j * 8 + (l & 3) * 2;
                    const float b0 = *(const float*)(sm + BIASOFF + col * 4);
                    const float b1 = *(const float*)(sm + BIASOFF + col * 4 + 4);
                    const int q = mt * 32 + j * 4;
                    float v00 = acc[q+0] + b0, v01 = acc[q+1] + b1;
                    float v10 = acc[q+2] + b0, v11 = acc[q+3] + b1;
                    v00 = v00 > 0.f ? v00 : expm1f(v00);
                    v01 = v01 > 0.f ? v01 : expm1f(v01);
                    v10 = v10 > 0.f ? v10 : expm1f(v10);
                    v11 = v11 > 0.f ? v11 : expm1f(v11);
                    __nv_bfloat16 h0,h1,h2,h3,e0,e1,e2,e3;
                    split1(v00,h0,e0); split1(v01,h1,e1); split1(v10,h2,e2); split1(v11,h3,e3);
                    *(uint32_t*)(outHi + (base + r0) * N + col)     = pack2(h0, h1);
                    *(uint32_t*)(outLo + (base + r0) * N + col)     = pack2(e0, e1);
                    *(uint32_t*)(outHi + (base + r0 + 8) * N + col) = pack2(h2, h3);
                    *(uint32_t*)(outLo + (base + r0 + 8) * N + col) = pack2(e2, e3);
                }
            }
        }
        __syncthreads();
    }
}

// ============================ Layer 4 + fused dot ============================
__global__ void __launch_bounds__(512, 1)
l4_kernel(const __nv_bfloat16* __restrict__ inHi, const __nv_bfloat16* __restrict__ inLo,
          const float* __restrict__ bias, const float* __restrict__ x, float* __restrict__ outv)
{
    extern __shared__ char sm[];
    constexpr int K = 256, KT = 4, ZOFF = 131328;
    const int tid = threadIdx.x, wid = tid >> 5, l = tid & 31;
    const long base = (long)blockIdx.x * 128;
    const uint32_t smb = smem_u32(sm);

    auto prefA = [&](int kt, int buf) {
        const int k0 = kt * 64;
        #pragma unroll
        for (int i = tid; i < 2048; i += 512) {
            const int plane = i >> 10, j = i & 1023;
            const int r = j >> 3, c = j & 7;
            const __nv_bfloat16* src = (plane ? inLo : inHi) + (base + r) * K + k0 + c * 8;
            CP16(smb + buf * 32768 + plane * 16384 + r * 128 + ((uint32_t)(c ^ (r & 7)) << 4), src);
        }
    };

    #pragma unroll
    for (int i = tid; i < 4096; i += 512) {
        const int plane = i >> 11, j = i & 2047;
        const int n = j >> 5, c = j & 31;
        const __nv_bfloat16* src = (plane ? g_Wlo : g_Whi) + 425984 + n * 256 + c * 8;
        CP16(smb + 65536 + plane * 32768 + n * 512 + (((uint32_t)(c ^ (n & 7))) << 4), src);
    }
    prefA(0, 0); CP_COMMIT();
    if (tid < 64) *(float*)(sm + 131072 + tid * 4) = bias[tid];

    const int wM = (wid & 7) * 16, wN = (wid >> 3) * 32;
    const int aRow = wM + (l & 15), aCk = l >> 4;
    const uint32_t aSel = (uint32_t)(aRow & 7);
    const int bnLoc = (l & 7) | ((l & 16) >> 1), bcLoc = (l >> 3) & 1;

    float acc[16];
    #pragma unroll
    for (int q = 0; q < 16; q++) acc[q] = 0.0f;

    #pragma unroll 1
    for (int kt = 0; kt < KT; ++kt) {
        if (kt + 1 < KT) { prefA(kt + 1, (kt + 1) & 1); CP_COMMIT(); CP_WAIT1(); }
        else              CP_WAIT0();
        __syncthreads();
        const uint32_t ab = smb + (kt & 1) * 32768;
        #pragma unroll
        for (int s = 0; s < 4; s++) {
            const int ck = s * 2 + aCk;
            uint32_t ahi[4], alo[4];
            const uint32_t aaddr = ab + aRow * 128 + ((uint32_t)(ck ^ aSel) << 4);
            ldsm4(ahi, aaddr); ldsm4(alo, aaddr + 16384);
            const int bck = kt * 8 + s * 2 + bcLoc;
            uint32_t bh[4][2], bl[4][2], t[4];
            #pragma unroll
            for (int pp = 0; pp < 2; pp++) {
                const int n = wN + 16 * pp + bnLoc;
                const uint32_t ba = smb + 65536 + n * 512 + ((uint32_t)(bck ^ (n & 7)) << 4);
                ldsm4(t, ba);
                bh[2*pp][0]=t[0]; bh[2*pp][1]=t[1]; bh[2*pp+1][0]=t[2]; bh[2*pp+1][1]=t[3];
                ldsm4(t, ba + 32768);
                bl[2*pp][0]=t[0]; bl[2*pp][1]=t[1]; bl[2*pp+1][0]=t[2]; bl[2*pp+1][1]=t[3];
            }
            #pragma unroll
            for (int u = 0; u < 4; u++) mma_bf16(acc + 4*u, ahi, bh[u]);
            #pragma unroll
            for (int u = 0; u < 4; u++) mma_bf16(acc + 4*u, ahi, bl[u]);
            #pragma unroll
            for (int u = 0; u < 4; u++) mma_bf16(acc + 4*u, alo, bh[u]);
        }
        __syncthreads();
    }

    float* zb = (float*)(sm + ZOFF);
    const int r0 = wM + (l >> 2);
    #pragma unroll
    for (int j = 0; j < 4; j++) {
        const int col = wN + j * 8 + (l & 3) * 2;
        const float b0 = *(const float*)(sm + 131072 + col * 4);
        const float b1 = *(const float*)(sm + 131072 + col * 4 + 4);
        zb[r0 * 66 + col]           = acc[4*j+0] + b0;
        zb[r0 * 66 + col + 1]       = acc[4*j+1] + b1;
        zb[(r0 + 8) * 66 + col]     = acc[4*j+2] + b0;
        zb[(r0 + 8) * 66 + col + 1] = acc[4*j+3] + b1;
    }
    __syncthreads();
    if (tid < 128) {
        const float4* xr = (const float4*)(x + (base + tid) * 64);
        const float* zr = zb + tid * 66;
        float s = 0.0f;
        #pragma unroll
        for (int q = 0; q < 16; q++) {
            const float4 xv = xr[q];
            s += xv.x * zr[q*4+0] + xv.y * zr[q*4+1] + xv.z * zr[q*4+2] + xv.w * zr[q*4+3];
        }
        outv[base + tid] = -s * s;
    }
}

extern "C" void kernel_launch(void* const* d_in, const int* in_sizes, int n_in,
                              void* d_out, int out_size)
{
    const float* x  = (const float*)d_in[0];
    const float* W1 = (const float*)d_in[1];
    const float* b1 = (const float*)d_in[2];
    const float* W2 = (const float*)d_in[3];
    const float* b2 = (const float*)d_in[4];
    const float* W3 = (const float*)d_in[5];
    const float* b3 = (const float*)d_in[6];
    const float* W4 = (const float*)d_in[7];
    const float* b4 = (const float*)d_in[8];
    float* out = (float*)d_out;

    __nv_bfloat16 *hiA, *loA, *hiB, *loB;
    cudaGetSymbolAddress((void**)&hiA, g_hiA);
    cudaGetSymbolAddress((void**)&loA, g_loA);
    cudaGetSymbolAddress((void**)&hiB, g_hiB);
    cudaGetSymbolAddress((void**)&loB, g_loB);

    split_all<<<(442368 + 511) / 512, 512>>>(W1, W2, W3, W4);

    constexpr int SZ1 = 165888;
    constexpr int SZM = 198656;
    constexpr int SZ4 = 165120;
    cudaFuncSetAttribute(l1_kernel,       cudaFuncAttributeMaxDynamicSharedMemorySize, SZ1);
    cudaFuncSetAttribute(mid_kernel<512>, cudaFuncAttributeMaxDynamicSharedMemorySize, SZM);
    cudaFuncSetAttribute(mid_kernel<256>, cudaFuncAttributeMaxDynamicSharedMemorySize, SZM);
    cudaFuncSetAttribute(l4_kernel,       cudaFuncAttributeMaxDynamicSharedMemorySize, SZ4);

    const int grid = 65536 / 128;  // 512
    l1_kernel<<<grid, 512, SZ1>>>(x, b1, hiA, loA);
    mid_kernel<512><<<grid, 512, SZM>>>(hiA, loA, 32768,  b2, hiB, loB);
    mid_kernel<256><<<grid, 512, SZM>>>(hiB, loB, 294912, b3, hiA, loA);
    l4_kernel<<<grid, 512, SZ4>>>(hiA, loA, b4, x, out);
}

// round 7
// speedup vs baseline: 6.6964x; 1.1163x over previous
#include <cuda_runtime.h>
#include <cuda_bf16.h>
#include <cstdint>

// value[b] = -( x[b] . MLP(x[b]) )^2 — HMMA bf16 hi/lo split GEMM chain.
// R7: 256 thr/CTA, M_CTA=64, smem <= ~100KB -> 2 CTAs/SM to overlap barrier bubbles.

__device__ __nv_bfloat16 g_Whi[442368];
__device__ __nv_bfloat16 g_Wlo[442368];
__device__ __nv_bfloat16 g_hiA[65536UL * 512];
__device__ __nv_bfloat16 g_loA[65536UL * 512];
__device__ __nv_bfloat16 g_hiB[65536UL * 512];
__device__ __nv_bfloat16 g_loB[65536UL * 512];

__device__ __forceinline__ uint32_t smem_u32(const void* p) {
    uint32_t a;
    asm("{ .reg .u64 t; cvta.to.shared.u64 t, %1; cvt.u32.u64 %0, t; }" : "=r"(a) : "l"(p));
    return a;
}
__device__ __forceinline__ void ldsm4(uint32_t* r, uint32_t addr) {
    asm volatile("ldmatrix.sync.aligned.m8n8.x4.shared.b16 {%0,%1,%2,%3}, [%4];"
        : "=r"(r[0]), "=r"(r[1]), "=r"(r[2]), "=r"(r[3]) : "r"(addr));
}
__device__ __forceinline__ void mma_bf16(float* c, const uint32_t* a, const uint32_t* b) {
    asm volatile("mma.sync.aligned.m16n8k16.row.col.f32.bf16.bf16.f32 "
        "{%0,%1,%2,%3}, {%4,%5,%6,%7}, {%8,%9}, {%0,%1,%2,%3};"
        : "+f"(c[0]), "+f"(c[1]), "+f"(c[2]), "+f"(c[3])
        : "r"(a[0]), "r"(a[1]), "r"(a[2]), "r"(a[3]), "r"(b[0]), "r"(b[1]));
}
#define CP16(dst, src)  asm volatile("cp.async.cg.shared.global [%0], [%1], 16;" :: "r"(dst), "l"(src))
#define CP_COMMIT()     asm volatile("cp.async.commit_group;" ::: "memory")
#define CP_WAIT1()      asm volatile("cp.async.wait_group 1;" ::: "memory")
#define CP_WAIT0()      asm volatile("cp.async.wait_group 0;" ::: "memory")

__device__ __forceinline__ uint32_t pack2(__nv_bfloat16 a, __nv_bfloat16 b) {
    return (uint32_t)__bfloat16_as_ushort(a) | ((uint32_t)__bfloat16_as_ushort(b) << 16);
}
__device__ __forceinline__ void split1(float v, __nv_bfloat16& h, __nv_bfloat16& l) {
    h = __float2bfloat16(v);
    l = __float2bfloat16(v - __bfloat162float(h));
}

__global__ void split_all(const float* __restrict__ W1, const float* __restrict__ W2,
                          const float* __restrict__ W3, const float* __restrict__ W4) {
    int i = blockIdx.x * blockDim.x + threadIdx.x;
    if (i >= 442368) return;
    float w;
    if (i < 32768)       w = W1[i];
    else if (i < 294912) w = W2[i - 32768];
    else if (i < 425984) w = W3[i - 294912];
    else                 w = W4[i - 425984];
    __nv_bfloat16 h, l; split1(w, h, l);
    g_Whi[i] = h; g_Wlo[i] = l;
}

// ============================ Layer 1: x(f32,K=64) -> 512, ELU ============================
// A resident (16KB hi/lo), W streamed NT=128 double-buffered. smem 83968 -> 2 CTAs/SM.
__global__ void __launch_bounds__(256, 2)
l1_kernel(const float* __restrict__ x, const float* __restrict__ bias,
          __nv_bfloat16* __restrict__ outHi, __nv_bfloat16* __restrict__ outLo)
{
    extern __shared__ char sm[];
    // [0,16384) A hi/lo | [16384,81920) W bufs 2x(hi16K+lo16K) | [81920,83968) bias
    const int tid = threadIdx.x, wid = tid >> 5, l = tid & 31;
    const long base = (long)blockIdx.x * 64;
    const uint32_t smb = smem_u32(sm);

    auto prefW = [&](int nt, int buf) {
        const int n0 = nt * 128;
        #pragma unroll
        for (int i = tid; i < 2048; i += 256) {
            const int plane = i >> 10, j = i & 1023;
            const int n = j >> 3, c = j & 7;
            const __nv_bfloat16* src = (plane ? g_Wlo : g_Whi) + (n0 + n) * 64 + c * 8;
            CP16(smb + 16384 + buf * 32768 + plane * 16384 + n * 128 + ((uint32_t)(c ^ (n & 7)) << 4), src);
        }
    };

    prefW(0, 0); CP_COMMIT();

    // A: convert fp32 x -> hi/lo planes (swizzled): 64 rows x 16 f4
    #pragma unroll
    for (int i = tid; i < 1024; i += 256) {
        const int r = i >> 4, k4 = (i & 15) * 4;
        const int c = k4 >> 3, wi = (k4 & 4) << 1;
        const float4 v = *(const float4*)(x + (base + r) * 64 + k4);
        __nv_bfloat16 h0, h1, h2, h3, e0, e1, e2, e3;
        split1(v.x, h0, e0); split1(v.y, h1, e1); split1(v.z, h2, e2); split1(v.w, h3, e3);
        const uint32_t off = r * 128 + ((uint32_t)(c ^ (r & 7)) << 4) + wi;
        *(uint32_t*)(sm + off)            = pack2(h0, h1);
        *(uint32_t*)(sm + off + 4)        = pack2(h2, h3);
        *(uint32_t*)(sm + 8192 + off)     = pack2(e0, e1);
        *(uint32_t*)(sm + 8192 + off + 4) = pack2(e2, e3);
    }
    for (int i = tid; i < 512; i += 256) *(float*)(sm + 81920 + i * 4) = bias[i];

    const int wM = (wid & 1) * 32, wN = (wid >> 1) * 32;
    const int aRow = wM + (l & 15), aCk = l >> 4;
    const uint32_t aSel = (uint32_t)(aRow & 7);
    const int bnLoc = (l & 7) | ((l & 16) >> 1), bcLoc = (l >> 3) & 1;

    #pragma unroll 1
    for (int nt = 0; nt < 4; nt++) {
        if (nt + 1 < 4) { prefW(nt + 1, (nt + 1) & 1); CP_COMMIT(); CP_WAIT1(); }
        else             CP_WAIT0();
        __syncthreads();
        const uint32_t wb = smb + 16384 + (nt & 1) * 32768;

        float acc[32];
        #pragma unroll
        for (int q = 0; q < 32; q++) acc[q] = 0.0f;

        #pragma unroll
        for (int s = 0; s < 4; s++) {
            const int ck = s * 2 + aCk;
            uint32_t ahi[2][4], alo[2][4];
            #pragma unroll
            for (int mt = 0; mt < 2; mt++) {
                const uint32_t aaddr = smb + (aRow + mt * 16) * 128 + ((uint32_t)(ck ^ aSel) << 4);
                ldsm4(ahi[mt], aaddr); ldsm4(alo[mt], aaddr + 8192);
            }
            const int bc = s * 2 + bcLoc;
            uint32_t bh[4][2], bl[4][2], t[4];
            #pragma unroll
            for (int pp = 0; pp < 2; pp++) {
                const int n = wN + 16 * pp + bnLoc;
                const uint32_t ba = wb + n * 128 + ((uint32_t)(bc ^ (n & 7)) << 4);
                ldsm4(t, ba);
                bh[2*pp][0]=t[0]; bh[2*pp][1]=t[1]; bh[2*pp+1][0]=t[2]; bh[2*pp+1][1]=t[3];
                ldsm4(t, ba + 16384);
                bl[2*pp][0]=t[0]; bl[2*pp][1]=t[1]; bl[2*pp+1][0]=t[2]; bl[2*pp+1][1]=t[3];
            }
            #pragma unroll
            for (int mt = 0; mt < 2; mt++) {
                float* am = acc + mt * 16;
                #pragma unroll
                for (int u = 0; u < 4; u++) mma_bf16(am + 4*u, ahi[mt], bh[u]);
                #pragma unroll
                for (int u = 0; u < 4; u++) mma_bf16(am + 4*u, ahi[mt], bl[u]);
                #pragma unroll
                for (int u = 0; u < 4; u++) mma_bf16(am + 4*u, alo[mt], bh[u]);
            }
        }
        #pragma unroll
        for (int mt = 0; mt < 2; mt++) {
            const int r0 = wM + mt * 16 + (l >> 2);
            #pragma unroll
            for (int j = 0; j < 4; j++) {
                const int col = nt * 128 + wN + j * 8 + (l & 3) * 2;
                const float b0 = *(const float*)(sm + 81920 + col * 4);
                const float b1 = *(const float*)(sm + 81920 + col * 4 + 4);
                const int q = mt * 16 + j * 4;
                float v00 = acc[q+0] + b0, v01 = acc[q+1] + b1;
                float v10 = acc[q+2] + b0, v11 = acc[q+3] + b1;
                v00 = v00 > 0.f ? v00 : expm1f(v00);
                v01 = v01 > 0.f ? v01 : expm1f(v01);
                v10 = v10 > 0.f ? v10 : expm1f(v10);
                v11 = v11 > 0.f ? v11 : expm1f(v11);
                __nv_bfloat16 h0,h1,h2,h3,e0,e1,e2,e3;
                split1(v00,h0,e0); split1(v01,h1,e1); split1(v10,h2,e2); split1(v11,h3,e3);
                *(uint32_t*)(outHi + (base + r0) * 512 + col)     = pack2(h0, h1);
                *(uint32_t*)(outLo + (base + r0) * 512 + col)     = pack2(e0, e1);
                *(uint32_t*)(outHi + (base + r0 + 8) * 512 + col) = pack2(h2, h3);
                *(uint32_t*)(outLo + (base + r0 + 8) * 512 + col) = pack2(e2, e3);
            }
        }
        __syncthreads();
    }
}

// ============================ Mid layers: K=512 -> N (ELU) ============================
// M_CTA=64, NT=128, A+W double-buffered. smem <=100352 -> 2 CTAs/SM.
template<int N>
__global__ void __launch_bounds__(256, 2)
mid_kernel(const __nv_bfloat16* __restrict__ inHi, const __nv_bfloat16* __restrict__ inLo,
           int woff, const float* __restrict__ bias,
           __nv_bfloat16* __restrict__ outHi, __nv_bfloat16* __restrict__ outLo)
{
    extern __shared__ char sm[];
    constexpr int K = 512, KT = 8, NITER = (N / 128) * KT;
    // [0,32768) A bufs 2x(hi8K+lo8K) | [32768,98304) W bufs 2x(hi16K+lo16K) | bias
    constexpr int BIASOFF = 98304;

    const int tid = threadIdx.x, wid = tid >> 5, l = tid & 31;
    const long base = (long)blockIdx.x * 64;
    const uint32_t smb = smem_u32(sm);

    auto prefetch = [&](int it, int buf) {
        const int nt = it / KT, kt = it % KT;
        const int k0 = kt * 64, n0 = nt * 128;
        #pragma unroll
        for (int i = tid; i < 1024; i += 256) {        // A: 64 rows x 8 x 2 planes
            const int plane = i >> 9, j = i & 511;
            const int r = j >> 3, c = j & 7;
            const __nv_bfloat16* src = (plane ? inLo : inHi) + (base + r) * K + k0 + c * 8;
            CP16(smb + buf * 16384 + plane * 8192 + r * 128 + ((uint32_t)(c ^ (r & 7)) << 4), src);
        }
        #pragma unroll
        for (int i = tid; i < 2048; i += 256) {        // W: 128 rows x 8 x 2 planes
            const int plane = i >> 10, j = i & 1023;
            const int n = j >> 3, c = j & 7;
            const __nv_bfloat16* src = (plane ? g_Wlo : g_Whi) + woff + (long)(n0 + n) * K + k0 + c * 8;
            CP16(smb + 32768 + buf * 32768 + plane * 16384 + n * 128 + ((uint32_t)(c ^ (n & 7)) << 4), src);
        }
    };

    prefetch(0, 0); CP_COMMIT();
    for (int i = tid; i < N; i += 256) *(float*)(sm + BIASOFF + i * 4) = bias[i];

    const int wM = (wid & 1) * 32, wN = (wid >> 1) * 32;
    const int aRow = wM + (l & 15), aCk = l >> 4;
    const uint32_t aSel = (uint32_t)(aRow & 7);
    const int bnLoc = (l & 7) | ((l & 16) >> 1), bcLoc = (l >> 3) & 1;

    float acc[32];

    #pragma unroll 1
    for (int it = 0; it < NITER; ++it) {
        const int nt = it / KT, kt = it % KT;
        if (it + 1 < NITER) { prefetch(it + 1, (it + 1) & 1); CP_COMMIT(); CP_WAIT1(); }
        else                 CP_WAIT0();
        __syncthreads();
        if (kt == 0) {
            #pragma unroll
            for (int q = 0; q < 32; q++) acc[q] = 0.0f;
        }
        const uint32_t ab = smb + (it & 1) * 16384;
        const uint32_t wb = smb + 32768 + (it & 1) * 32768;
        #pragma unroll
        for (int s = 0; s < 4; s++) {
            const int ck = s * 2 + aCk;
            uint32_t ahi[2][4], alo[2][4];
            #pragma unroll
            for (int mt = 0; mt < 2; mt++) {
                const uint32_t aaddr = ab + (aRow + mt * 16) * 128 + ((uint32_t)(ck ^ aSel) << 4);
                ldsm4(ahi[mt], aaddr); ldsm4(alo[mt], aaddr + 8192);
            }
            const int bc = s * 2 + bcLoc;
            uint32_t bh[4][2], bl[4][2], t[4];
            #pragma unroll
            for (int pp = 0; pp < 2; pp++) {
                const int n = wN + 16 * pp + bnLoc;
                const uint32_t ba = wb + n * 128 + ((uint32_t)(bc ^ (n & 7)) << 4);
                ldsm4(t, ba);
                bh[2*pp][0]=t[0]; bh[2*pp][1]=t[1]; bh[2*pp+1][0]=t[2]; bh[2*pp+1][1]=t[3];
                ldsm4(t, ba + 16384);
                bl[2*pp][0]=t[0]; bl[2*pp][1]=t[1]; bl[2*pp+1][0]=t[2]; bl[2*pp+1][1]=t[3];
            }
            #pragma unroll
            for (int mt = 0; mt < 2; mt++) {
                float* am = acc + mt * 16;
                #pragma unroll
                for (int u = 0; u < 4; u++) mma_bf16(am + 4*u, ahi[mt], bh[u]);
                #pragma unroll
                for (int u = 0; u < 4; u++) mma_bf16(am + 4*u, ahi[mt], bl[u]);
                #pragma unroll
                for (int u = 0; u < 4; u++) mma_bf16(am + 4*u, alo[mt], bh[u]);
            }
        }
        if (kt == KT - 1) {
            #pragma unroll
            for (int mt = 0; mt < 2; mt++) {
                const int r0 = wM + mt * 16 + (l >> 2);
                #pragma unroll
                for (int j = 0; j < 4; j++) {
                    const int col = nt * 128 + wN + j * 8 + (l & 3) * 2;
                    const float b0 = *(const float*)(sm + BIASOFF + col * 4);
                    const float b1 = *(const float*)(sm + BIASOFF + col * 4 + 4);
                    const int q = mt * 16 + j * 4;
                    float v00 = acc[q+0] + b0, v01 = acc[q+1] + b1;
                    float v10 = acc[q+2] + b0, v11 = acc[q+3] + b1;
                    v00 = v00 > 0.f ? v00 : expm1f(v00);
                    v01 = v01 > 0.f ? v01 : expm1f(v01);
                    v10 = v10 > 0.f ? v10 : expm1f(v10);
                    v11 = v11 > 0.f ? v11 : expm1f(v11);
                    __nv_bfloat16 h0,h1,h2,h3,e0,e1,e2,e3;
                    split1(v00,h0,e0); split1(v01,h1,e1); split1(v10,h2,e2); split1(v11,h3,e3);
                    *(uint32_t*)(outHi + (base + r0) * N + col)     = pack2(h0, h1);
                    *(uint32_t*)(outLo + (base + r0) * N + col)     = pack2(e0, e1);
                    *(uint32_t*)(outHi + (base + r0 + 8) * N + col) = pack2(h2, h3);
                    *(uint32_t*)(outLo + (base + r0 + 8) * N + col) = pack2(e2, e3);
                }
            }
        }
        __syncthreads();
    }
}

// ============================ Layer 4 + fused dot: K=256 -> 64, out=-(x.z)^2 ============================
// W4 resident (64KB), A streamed. Lane-local x-weighted dot, quad shfl reduce, smem slots.
__global__ void __launch_bounds__(256, 2)
l4_kernel(const __nv_bfloat16* __restrict__ inHi, const __nv_bfloat16* __restrict__ inLo,
          const float* __restrict__ bias, const float* __restrict__ x, float* __restrict__ outv)
{
    extern __shared__ char sm[];
    // [0,32768) A bufs 2x(hi8K+lo8K) | [32768,98304) W hi32K+lo32K | [98304,98560) bias | [98560,99584) zsum
    constexpr int KT = 4;
    const int tid = threadIdx.x, wid = tid >> 5, l = tid & 31;
    const long base = (long)blockIdx.x * 64;
    const uint32_t smb = smem_u32(sm);

    auto prefA = [&](int kt, int buf) {
        const int k0 = kt * 64;
        #pragma unroll
        for (int i = tid; i < 1024; i += 256) {
            const int plane = i >> 9, j = i & 511;
            const int r = j >> 3, c = j & 7;
            const __nv_bfloat16* src = (plane ? inLo : inHi) + (base + r) * 256 + k0 + c * 8;
            CP16(smb + buf * 16384 + plane * 8192 + r * 128 + ((uint32_t)(c ^ (r & 7)) << 4), src);
        }
    };

    // W4 resident: 64 rows x 32 chunks x 2 planes (row stride 512B)
    #pragma unroll
    for (int i = tid; i < 4096; i += 256) {
        const int plane = i >> 11, j = i & 2047;
        const int n = j >> 5, c = j & 31;
        const __nv_bfloat16* src = (plane ? g_Wlo : g_Whi) + 425984 + n * 256 + c * 8;
        CP16(smb + 32768 + plane * 32768 + n * 512 + (((uint32_t)(c ^ (n & 7))) << 4), src);
    }
    prefA(0, 0); CP_COMMIT();
    if (tid < 64) *(float*)(sm + 98304 + tid * 4) = bias[tid];

    const int wM = (wid & 1) * 32, wN = (wid >> 1) * 16;
    const int aRow = wM + (l & 15), aCk = l >> 4;
    const uint32_t aSel = (uint32_t)(aRow & 7);
    const int bnLoc = (l & 7) | ((l & 16) >> 1), bcLoc = (l >> 3) & 1;

    float acc[16];
    #pragma unroll
    for (int q = 0; q < 16; q++) acc[q] = 0.0f;

    #pragma unroll 1
    for (int kt = 0; kt < KT; ++kt) {
        if (kt + 1 < KT) { prefA(kt + 1, (kt + 1) & 1); CP_COMMIT(); CP_WAIT1(); }
        else              CP_WAIT0();
        __syncthreads();
        const uint32_t ab = smb + (kt & 1) * 16384;
        #pragma unroll
        for (int s = 0; s < 4; s++) {
            const int ck = s * 2 + aCk;
            uint32_t ahi[2][4], alo[2][4];
            #pragma unroll
            for (int mt = 0; mt < 2; mt++) {
                const uint32_t aaddr = ab + (aRow + mt * 16) * 128 + ((uint32_t)(ck ^ aSel) << 4);
                ldsm4(ahi[mt], aaddr); ldsm4(alo[mt], aaddr + 8192);
            }
            const int bck = kt * 8 + s * 2 + bcLoc;
            uint32_t bh[2][2], bl[2][2], t[4];
            {
                const int n = wN + bnLoc;
                const uint32_t ba = smb + 32768 + n * 512 + ((uint32_t)(bck ^ (n & 7)) << 4);
                ldsm4(t, ba);
                bh[0][0]=t[0]; bh[0][1]=t[1]; bh[1][0]=t[2]; bh[1][1]=t[3];
                ldsm4(t, ba + 32768);
                bl[0][0]=t[0]; bl[0][1]=t[1]; bl[1][0]=t[2]; bl[1][1]=t[3];
            }
            #pragma unroll
            for (int mt = 0; mt < 2; mt++) {
                float* am = acc + mt * 8;
                #pragma unroll
                for (int u = 0; u < 2; u++) mma_bf16(am + 4*u, ahi[mt], bh[u]);
                #pragma unroll
                for (int u = 0; u < 2; u++) mma_bf16(am + 4*u, ahi[mt], bl[u]);
                #pragma unroll
                for (int u = 0; u < 2; u++) mma_bf16(am + 4*u, alo[mt], bh[u]);
            }
        }
        __syncthreads();
    }

    // Lane-local x-weighted dot over this lane's fragment columns, then reduce.
    float* zsum = (float*)(sm + 98560);   // [64 rows][4 n-warp slots]
    #pragma unroll
    for (int mt = 0; mt < 2; mt++) {
        const int r0 = wM + mt * 16 + (l >> 2);
        float p0 = 0.0f, p1 = 0.0f;
        #pragma unroll
        for (int u = 0; u < 2; u++) {
            const int col = wN + u * 8 + (l & 3) * 2;
            const float b0 = *(const float*)(sm + 98304 + col * 4);
            const float b1 = *(const float*)(sm + 98304 + col * 4 + 4);
            const int q = mt * 8 + u * 4;
            const float2 x0 = *(const float2*)(x + (base + r0) * 64 + col);
            const float2 x1 = *(const float2*)(x + (base + r0 + 8) * 64 + col);
            p0 += (acc[q+0] + b0) * x0.x + (acc[q+1] + b1) * x0.y;
            p1 += (acc[q+2] + b0) * x1.x + (acc[q+3] + b1) * x1.y;
        }
        p0 += __shfl_xor_sync(0xFFFFFFFF, p0, 1);
        p0 += __shfl_xor_sync(0xFFFFFFFF, p0, 2);
        p1 += __shfl_xor_sync(0xFFFFFFFF, p1, 1);
        p1 += __shfl_xor_sync(0xFFFFFFFF, p1, 2);
        if ((l & 3) == 0) {
            zsum[r0 * 4 + (wid >> 1)]       = p0;
            zsum[(r0 + 8) * 4 + (wid >> 1)] = p1;
        }
    }
    __syncthreads();
    if (tid < 64) {
        const float s = zsum[tid * 4] + zsum[tid * 4 + 1] + zsum[tid * 4 + 2] + zsum[tid * 4 + 3];
        outv[base + tid] = -s * s;
    }
}

extern "C" void kernel_launch(void* const* d_in, const int* in_sizes, int n_in,
                              void* d_out, int out_size)
{
    const float* x  = (const float*)d_in[0];
    const float* W1 = (const float*)d_in[1];
    const float* b1 = (const float*)d_in[2];
    const float* W2 = (const float*)d_in[3];
    const float* b2 = (const float*)d_in[4];
    const float* W3 = (const float*)d_in[5];
    const float* b3 = (const float*)d_in[6];
    const float* W4 = (const float*)d_in[7];
    const float* b4 = (const float*)d_in[8];
    float* out = (float*)d_out;

    __nv_bfloat16 *hiA, *loA, *hiB, *loB;
    cudaGetSymbolAddress((void**)&hiA, g_hiA);
    cudaGetSymbolAddress((void**)&loA, g_loA);
    cudaGetSymbolAddress((void**)&hiB, g_hiB);
    cudaGetSymbolAddress((void**)&loB, g_loB);

    split_all<<<(442368 + 511) / 512, 512>>>(W1, W2, W3, W4);

    constexpr int SZ1 = 83968;    // 16K A + 64K W bufs + 2K bias
    constexpr int SZM5 = 100352;  // 32K A bufs + 64K W bufs + 2K bias
    constexpr int SZM2 = 99328;   // ... + 1K bias
    constexpr int SZ4 = 99584;    // 32K A bufs + 64K W + 256B bias + 1K zsum
    cudaFuncSetAttribute(l1_kernel,       cudaFuncAttributeMaxDynamicSharedMemorySize, SZ1);
    cudaFuncSetAttribute(mid_kernel<512>, cudaFuncAttributeMaxDynamicSharedMemorySize, SZM5);
    cudaFuncSetAttribute(mid_kernel<256>, cudaFuncAttributeMaxDynamicSharedMemorySize, SZM2);
    cudaFuncSetAttribute(l4_kernel,       cudaFuncAttributeMaxDynamicSharedMemorySize, SZ4);

    const int grid = 65536 / 64;  // 1024
    l1_kernel<<<grid, 256, SZ1>>>(x, b1, hiA, loA);
    mid_kernel<512><<<grid, 256, SZM5>>>(hiA, loA, 32768,  b2, hiB, loB);
    mid_kernel<256><<<grid, 256, SZM2>>>(hiB, loB, 294912, b3, hiA, loA);
    l4_kernel<<<grid, 256, SZ4>>>(hiA, loA, b4, x, out);
}

// round 8
// speedup vs baseline: 8.9401x; 1.3351x over previous
#include <cuda_runtime.h>
#include <cuda_fp16.h>
#include <cstdint>

// value[b] = -( x[b] . MLP(x[b]) )^2 — fp16 HMMA GEMM chain.
// R8: W = fp16 hi/lo split (exact to ~2^-21), activations = single fp16 (2^-11).
// Only 2 MMAs per k16 (a*Whi + a*Wlo) -> 33% less tensor work than bf16 3-MMA.

__device__ __half g_Whi[442368];
__device__ __half g_Wlo[442368];
__device__ __half g_actA[65536UL * 512];
__device__ __half g_actB[65536UL * 512];

__device__ __forceinline__ uint32_t smem_u32(const void* p) {
    uint32_t a;
    asm("{ .reg .u64 t; cvta.to.shared.u64 t, %1; cvt.u32.u64 %0, t; }" : "=r"(a) : "l"(p));
    return a;
}
__device__ __forceinline__ void ldsm4(uint32_t* r, uint32_t addr) {
    asm volatile("ldmatrix.sync.aligned.m8n8.x4.shared.b16 {%0,%1,%2,%3}, [%4];"
        : "=r"(r[0]), "=r"(r[1]), "=r"(r[2]), "=r"(r[3]) : "r"(addr));
}
__device__ __forceinline__ void mma_f16(float* c, const uint32_t* a, const uint32_t* b) {
    asm volatile("mma.sync.aligned.m16n8k16.row.col.f32.f16.f16.f32 "
        "{%0,%1,%2,%3}, {%4,%5,%6,%7}, {%8,%9}, {%0,%1,%2,%3};"
        : "+f"(c[0]), "+f"(c[1]), "+f"(c[2]), "+f"(c[3])
        : "r"(a[0]), "r"(a[1]), "r"(a[2]), "r"(a[3]), "r"(b[0]), "r"(b[1]));
}
#define CP16(dst, src)  asm volatile("cp.async.cg.shared.global [%0], [%1], 16;" :: "r"(dst), "l"(src))
#define CP_COMMIT()     asm volatile("cp.async.commit_group;" ::: "memory")
#define CP_WAIT1()      asm volatile("cp.async.wait_group 1;" ::: "memory")
#define CP_WAIT0()      asm volatile("cp.async.wait_group 0;" ::: "memory")

__device__ __forceinline__ uint32_t packh2(__half a, __half b) {
    return (uint32_t)__half_as_ushort(a) | ((uint32_t)__half_as_ushort(b) << 16);
}
__device__ __forceinline__ void split1h(float v, __half& h, __half& l) {
    h = __float2half_rn(v);
    l = __float2half_rn(v - __half2float(h));
}

__global__ void split_all(const float* __restrict__ W1, const float* __restrict__ W2,
                          const float* __restrict__ W3, const float* __restrict__ W4) {
    int i = blockIdx.x * blockDim.x + threadIdx.x;
    if (i >= 442368) return;
    float w;
    if (i < 32768)       w = W1[i];
    else if (i < 294912) w = W2[i - 32768];
    else if (i < 425984) w = W3[i - 294912];
    else                 w = W4[i - 425984];
    __half h, l; split1h(w, h, l);
    g_Whi[i] = h; g_Wlo[i] = l;
}

// ============================ Layer 1: x(f32,K=64) -> 512, ELU ============================
// A resident single fp16 plane (8KB), W streamed NT=128 dbl-buffered (hi/lo 32KB/buf).
__global__ void __launch_bounds__(256, 2)
l1_kernel(const float* __restrict__ x, const float* __restrict__ bias,
          __half* __restrict__ out)
{
    extern __shared__ char sm[];
    // [0,8192) A | [8192,73728) W bufs 2x(hi16K+lo16K) | [73728,75776) bias
    const int tid = threadIdx.x, wid = tid >> 5, l = tid & 31;
    const long base = (long)blockIdx.x * 64;
    const uint32_t smb = smem_u32(sm);

    auto prefW = [&](int nt, int buf) {
        const int n0 = nt * 128;
        #pragma unroll
        for (int i = tid; i < 2048; i += 256) {
            const int plane = i >> 10, j = i & 1023;
            const int n = j >> 3, c = j & 7;
            const __half* src = (plane ? g_Wlo : g_Whi) + (n0 + n) * 64 + c * 8;
            CP16(smb + 8192 + buf * 32768 + plane * 16384 + n * 128 + ((uint32_t)(c ^ (n & 7)) << 4), src);
        }
    };

    prefW(0, 0); CP_COMMIT();

    // A: fp32 x -> single fp16 plane, swizzled. 64 rows x 16 f4-groups.
    #pragma unroll
    for (int i = tid; i < 1024; i += 256) {
        const int r = i >> 4, k4 = (i & 15) * 4;
        const int c = k4 >> 3, wi = (k4 & 4) << 1;
        const float4 v = *(const float4*)(x + (base + r) * 64 + k4);
        const uint32_t off = r * 128 + ((uint32_t)(c ^ (r & 7)) << 4) + wi;
        *(uint32_t*)(sm + off)     = packh2(__float2half_rn(v.x), __float2half_rn(v.y));
        *(uint32_t*)(sm + off + 4) = packh2(__float2half_rn(v.z), __float2half_rn(v.w));
    }
    for (int i = tid; i < 512; i += 256) *(float*)(sm + 73728 + i * 4) = bias[i];

    const int wM = (wid & 1) * 32, wN = (wid >> 1) * 32;
    const int aRow = wM + (l & 15), aCk = l >> 4;
    const uint32_t aSel = (uint32_t)(aRow & 7);
    const int bnLoc = (l & 7) | ((l & 16) >> 1), bcLoc = (l >> 3) & 1;

    #pragma unroll 1
    for (int nt = 0; nt < 4; nt++) {
        if (nt + 1 < 4) { prefW(nt + 1, (nt + 1) & 1); CP_COMMIT(); CP_WAIT1(); }
        else             CP_WAIT0();
        __syncthreads();
        const uint32_t wb = smb + 8192 + (nt & 1) * 32768;

        float acc[32];
        #pragma unroll
        for (int q = 0; q < 32; q++) acc[q] = 0.0f;

        #pragma unroll
        for (int s = 0; s < 4; s++) {
            const int ck = s * 2 + aCk;
            uint32_t ah[2][4];
            #pragma unroll
            for (int mt = 0; mt < 2; mt++)
                ldsm4(ah[mt], smb + (aRow + mt * 16) * 128 + ((uint32_t)(ck ^ aSel) << 4));
            const int bc = s * 2 + bcLoc;
            uint32_t bh[4][2], bl[4][2], t[4];
            #pragma unroll
            for (int pp = 0; pp < 2; pp++) {
                const int n = wN + 16 * pp + bnLoc;
                const uint32_t ba = wb + n * 128 + ((uint32_t)(bc ^ (n & 7)) << 4);
                ldsm4(t, ba);
                bh[2*pp][0]=t[0]; bh[2*pp][1]=t[1]; bh[2*pp+1][0]=t[2]; bh[2*pp+1][1]=t[3];
                ldsm4(t, ba + 16384);
                bl[2*pp][0]=t[0]; bl[2*pp][1]=t[1]; bl[2*pp+1][0]=t[2]; bl[2*pp+1][1]=t[3];
            }
            #pragma unroll
            for (int mt = 0; mt < 2; mt++) {
                float* am = acc + mt * 16;
                #pragma unroll
                for (int u = 0; u < 4; u++) mma_f16(am + 4*u, ah[mt], bh[u]);
                #pragma unroll
                for (int u = 0; u < 4; u++) mma_f16(am + 4*u, ah[mt], bl[u]);
            }
        }
        #pragma unroll
        for (int mt = 0; mt < 2; mt++) {
            const int r0 = wM + mt * 16 + (l >> 2);
            #pragma unroll
            for (int j = 0; j < 4; j++) {
                const int col = nt * 128 + wN + j * 8 + (l & 3) * 2;
                const float b0 = *(const float*)(sm + 73728 + col * 4);
                const float b1 = *(const float*)(sm + 73728 + col * 4 + 4);
                const int q = mt * 16 + j * 4;
                float v00 = acc[q+0] + b0, v01 = acc[q+1] + b1;
                float v10 = acc[q+2] + b0, v11 = acc[q+3] + b1;
                v00 = v00 > 0.f ? v00 : expm1f(v00);
                v01 = v01 > 0.f ? v01 : expm1f(v01);
                v10 = v10 > 0.f ? v10 : expm1f(v10);
                v11 = v11 > 0.f ? v11 : expm1f(v11);
                *(uint32_t*)(out + (base + r0) * 512 + col)     = packh2(__float2half_rn(v00), __float2half_rn(v01));
                *(uint32_t*)(out + (base + r0 + 8) * 512 + col) = packh2(__float2half_rn(v10), __float2half_rn(v11));
            }
        }
        __syncthreads();
    }
}

// ============================ Mid layers: K=512 -> N (ELU) ============================
// A single fp16 plane streamed (8KB/buf), W hi/lo streamed (32KB/buf). 2 CTAs/SM.
template<int N>
__global__ void __launch_bounds__(256, 2)
mid_kernel(const __half* __restrict__ in, int woff, const float* __restrict__ bias,
           __half* __restrict__ out)
{
    extern __shared__ char sm[];
    constexpr int K = 512, KT = 8, NITER = (N / 128) * KT;
    // [0,16384) A bufs 2x8K | [16384,81920) W bufs 2x(hi16K+lo16K) | [81920,...) bias
    constexpr int BIASOFF = 81920;

    const int tid = threadIdx.x, wid = tid >> 5, l = tid & 31;
    const long base = (long)blockIdx.x * 64;
    const uint32_t smb = smem_u32(sm);

    auto prefetch = [&](int it, int buf) {
        const int nt = it / KT, kt = it % KT;
        const int k0 = kt * 64, n0 = nt * 128;
        #pragma unroll
        for (int i = tid; i < 512; i += 256) {         // A: 64 rows x 8 chunks
            const int r = i >> 3, c = i & 7;
            const __half* src = in + (base + r) * K + k0 + c * 8;
            CP16(smb + buf * 8192 + r * 128 + ((uint32_t)(c ^ (r & 7)) << 4), src);
        }
        #pragma unroll
        for (int i = tid; i < 2048; i += 256) {        // W: 128 rows x 8 x 2 planes
            const int plane = i >> 10, j = i & 1023;
            const int n = j >> 3, c = j & 7;
            const __half* src = (plane ? g_Wlo : g_Whi) + woff + (long)(n0 + n) * K + k0 + c * 8;
            CP16(smb + 16384 + buf * 32768 + plane * 16384 + n * 128 + ((uint32_t)(c ^ (n & 7)) << 4), src);
        }
    };

    prefetch(0, 0); CP_COMMIT();
    for (int i = tid; i < N; i += 256) *(float*)(sm + BIASOFF + i * 4) = bias[i];

    const int wM = (wid & 1) * 32, wN = (wid >> 1) * 32;
    const int aRow = wM + (l & 15), aCk = l >> 4;
    const uint32_t aSel = (uint32_t)(aRow & 7);
    const int bnLoc = (l & 7) | ((l & 16) >> 1), bcLoc = (l >> 3) & 1;

    float acc[32];

    #pragma unroll 1
    for (int it = 0; it < NITER; ++it) {
        const int nt = it / KT, kt = it % KT;
        if (it + 1 < NITER) { prefetch(it + 1, (it + 1) & 1); CP_COMMIT(); CP_WAIT1(); }
        else                 CP_WAIT0();
        __syncthreads();
        if (kt == 0) {
            #pragma unroll
            for (int q = 0; q < 32; q++) acc[q] = 0.0f;
        }
        const uint32_t ab = smb + (it & 1) * 8192;
        const uint32_t wb = smb + 16384 + (it & 1) * 32768;
        #pragma unroll
        for (int s = 0; s < 4; s++) {
            const int ck = s * 2 + aCk;
            uint32_t ah[2][4];
            #pragma unroll
            for (int mt = 0; mt < 2; mt++)
                ldsm4(ah[mt], ab + (aRow + mt * 16) * 128 + ((uint32_t)(ck ^ aSel) << 4));
            const int bc = s * 2 + bcLoc;
            uint32_t bh[4][2], bl[4][2], t[4];
            #pragma unroll
            for (int pp = 0; pp < 2; pp++) {
                const int n = wN + 16 * pp + bnLoc;
                const uint32_t ba = wb + n * 128 + ((uint32_t)(bc ^ (n & 7)) << 4);
                ldsm4(t, ba);
                bh[2*pp][0]=t[0]; bh[2*pp][1]=t[1]; bh[2*pp+1][0]=t[2]; bh[2*pp+1][1]=t[3];
                ldsm4(t, ba + 16384);
                bl[2*pp][0]=t[0]; bl[2*pp][1]=t[1]; bl[2*pp+1][0]=t[2]; bl[2*pp+1][1]=t[3];
            }
            #pragma unroll
            for (int mt = 0; mt < 2; mt++) {
                float* am = acc + mt * 16;
                #pragma unroll
                for (int u = 0; u < 4; u++) mma_f16(am + 4*u, ah[mt], bh[u]);
                #pragma unroll
                for (int u = 0; u < 4; u++) mma_f16(am + 4*u, ah[mt], bl[u]);
            }
        }
        if (kt == KT - 1) {
            #pragma unroll
            for (int mt = 0; mt < 2; mt++) {
                const int r0 = wM + mt * 16 + (l >> 2);
                #pragma unroll
                for (int j = 0; j < 4; j++) {
                    const int col = nt * 128 + wN + j * 8 + (l & 3) * 2;
                    const float b0 = *(const float*)(sm + BIASOFF + col * 4);
                    const float b1 = *(const float*)(sm + BIASOFF + col * 4 + 4);
                    const int q = mt * 16 + j * 4;
                    float v00 = acc[q+0] + b0, v01 = acc[q+1] + b1;
                    float v10 = acc[q+2] + b0, v11 = acc[q+3] + b1;
                    v00 = v00 > 0.f ? v00 : expm1f(v00);
                    v01 = v01 > 0.f ? v01 : expm1f(v01);
                    v10 = v10 > 0.f ? v10 : expm1f(v10);
                    v11 = v11 > 0.f ? v11 : expm1f(v11);
                    *(uint32_t*)(out + (base + r0) * N + col)     = packh2(__float2half_rn(v00), __float2half_rn(v01));
                    *(uint32_t*)(out + (base + r0 + 8) * N + col) = packh2(__float2half_rn(v10), __float2half_rn(v11));
                }
            }
        }
        __syncthreads();
    }
}

// ============================ Layer 4 + fused dot: K=256 -> 64, out=-(x.z)^2 ============================
__global__ void __launch_bounds__(256, 2)
l4_kernel(const __half* __restrict__ in, const float* __restrict__ bias,
          const float* __restrict__ x, float* __restrict__ outv)
{
    extern __shared__ char sm[];
    // [0,16384) A bufs 2x8K | [16384,81920) W4 hi32K+lo32K | [81920,82176) bias | [82176,83200) zsum
    constexpr int KT = 4;
    const int tid = threadIdx.x, wid = tid >> 5, l = tid & 31;
    const long base = (long)blockIdx.x * 64;
    const uint32_t smb = smem_u32(sm);

    auto prefA = [&](int kt, int buf) {
        const int k0 = kt * 64;
        #pragma unroll
        for (int i = tid; i < 512; i += 256) {
            const int r = i >> 3, c = i & 7;
            const __half* src = in + (base + r) * 256 + k0 + c * 8;
            CP16(smb + buf * 8192 + r * 128 + ((uint32_t)(c ^ (r & 7)) << 4), src);
        }
    };

    // W4 resident: 64 rows x 32 chunks x 2 planes (row stride 512B)
    #pragma unroll
    for (int i = tid; i < 4096; i += 256) {
        const int plane = i >> 11, j = i & 2047;
        const int n = j >> 5, c = j & 31;
        const __half* src = (plane ? g_Wlo : g_Whi) + 425984 + n * 256 + c * 8;
        CP16(smb + 16384 + plane * 32768 + n * 512 + (((uint32_t)(c ^ (n & 7))) << 4), src);
    }
    prefA(0, 0); CP_COMMIT();
    if (tid < 64) *(float*)(sm + 81920 + tid * 4) = bias[tid];

    const int wM = (wid & 1) * 32, wN = (wid >> 1) * 16;
    const int aRow = wM + (l & 15), aCk = l >> 4;
    const uint32_t aSel = (uint32_t)(aRow & 7);
    const int bnLoc = (l & 7) | ((l & 16) >> 1), bcLoc = (l >> 3) & 1;

    float acc[16];
    #pragma unroll
    for (int q = 0; q < 16; q++) acc[q] = 0.0f;

    #pragma unroll 1
    for (int kt = 0; kt < KT; ++kt) {
        if (kt + 1 < KT) { prefA(kt + 1, (kt + 1) & 1); CP_COMMIT(); CP_WAIT1(); }
        else              CP_WAIT0();
        __syncthreads();
        const uint32_t ab = smb + (kt & 1) * 8192;
        #pragma unroll
        for (int s = 0; s < 4; s++) {
            const int ck = s * 2 + aCk;
            uint32_t ah[2][4];
            #pragma unroll
            for (int mt = 0; mt < 2; mt++)
                ldsm4(ah[mt], ab + (aRow + mt * 16) * 128 + ((uint32_t)(ck ^ aSel) << 4));
            const int bck = kt * 8 + s * 2 + bcLoc;
            uint32_t bh[2][2], bl[2][2], t[4];
            {
                const int n = wN + bnLoc;
                const uint32_t ba = smb + 16384 + n * 512 + ((uint32_t)(bck ^ (n & 7)) << 4);
                ldsm4(t, ba);
                bh[0][0]=t[0]; bh[0][1]=t[1]; bh[1][0]=t[2]; bh[1][1]=t[3];
                ldsm4(t, ba + 32768);
                bl[0][0]=t[0]; bl[0][1]=t[1]; bl[1][0]=t[2]; bl[1][1]=t[3];
            }
            #pragma unroll
            for (int mt = 0; mt < 2; mt++) {
                float* am = acc + mt * 8;
                mma_f16(am + 0, ah[mt], bh[0]);
                mma_f16(am + 4, ah[mt], bh[1]);
            }
            #pragma unroll
            for (int mt = 0; mt < 2; mt++) {
                float* am = acc + mt * 8;
                mma_f16(am + 0, ah[mt], bl[0]);
                mma_f16(am + 4, ah[mt], bl[1]);
            }
        }
        __syncthreads();
    }

    // Lane-local x-weighted dot, quad shfl reduce, per-N-warp smem slots.
    float* zsum = (float*)(sm + 82176);   // [64 rows][4 slots]
    #pragma unroll
    for (int mt = 0; mt < 2; mt++) {
        const int r0 = wM + mt * 16 + (l >> 2);
        float p0 = 0.0f, p1 = 0.0f;
        #pragma unroll
        for (int u = 0; u < 2; u++) {
            const int col = wN + u * 8 + (l & 3) * 2;
            const float b0 = *(const float*)(sm + 81920 + col * 4);
            const float b1 = *(const float*)(sm + 81920 + col * 4 + 4);
            const int q = mt * 8 + u * 4;
            const float2 x0 = *(const float2*)(x + (base + r0) * 64 + col);
            const float2 x1 = *(const float2*)(x + (base + r0 + 8) * 64 + col);
            p0 += (acc[q+0] + b0) * x0.x + (acc[q+1] + b1) * x0.y;
            p1 += (acc[q+2] + b0) * x1.x + (acc[q+3] + b1) * x1.y;
        }
        p0 += __shfl_xor_sync(0xFFFFFFFF, p0, 1);
        p0 += __shfl_xor_sync(0xFFFFFFFF, p0, 2);
        p1 += __shfl_xor_sync(0xFFFFFFFF, p1, 1);
        p1 += __shfl_xor_sync(0xFFFFFFFF, p1, 2);
        if ((l & 3) == 0) {
            zsum[r0 * 4 + (wid >> 1)]       = p0;
            zsum[(r0 + 8) * 4 + (wid >> 1)] = p1;
        }
    }
    __syncthreads();
    if (tid < 64) {
        const float s = zsum[tid * 4] + zsum[tid * 4 + 1] + zsum[tid * 4 + 2] + zsum[tid * 4 + 3];
        outv[base + tid] = -s * s;
    }
}

extern "C" void kernel_launch(void* const* d_in, const int* in_sizes, int n_in,
                              void* d_out, int out_size)
{
    const float* x  = (const float*)d_in[0];
    const float* W1 = (const float*)d_in[1];
    const float* b1 = (const float*)d_in[2];
    const float* W2 = (const float*)d_in[3];
    const float* b2 = (const float*)d_in[4];
    const float* W3 = (const float*)d_in[5];
    const float* b3 = (const float*)d_in[6];
    const float* W4 = (const float*)d_in[7];
    const float* b4 = (const float*)d_in[8];
    float* out = (float*)d_out;

    __half *actA, *actB;
    cudaGetSymbolAddress((void**)&actA, g_actA);
    cudaGetSymbolAddress((void**)&actB, g_actB);

    split_all<<<(442368 + 511) / 512, 512>>>(W1, W2, W3, W4);

    constexpr int SZ1 = 75776;   // 8K A + 64K W bufs + 2K bias
    constexpr int SZM5 = 83968;  // 16K A bufs + 64K W bufs + 2K bias
    constexpr int SZM2 = 82944;  // ... + 1K bias
    constexpr int SZ4 = 83200;   // 16K A bufs + 64K W + 256B bias + 1K zsum
    cudaFuncSetAttribute(l1_kernel,       cudaFuncAttributeMaxDynamicSharedMemorySize, SZ1);
    cudaFuncSetAttribute(mid_kernel<512>, cudaFuncAttributeMaxDynamicSharedMemorySize, SZM5);
    cudaFuncSetAttribute(mid_kernel<256>, cudaFuncAttributeMaxDynamicSharedMemorySize, SZM2);
    cudaFuncSetAttribute(l4_kernel,       cudaFuncAttributeMaxDynamicSharedMemorySize, SZ4);

    const int grid = 65536 / 64;  // 1024
    l1_kernel<<<grid, 256, SZ1>>>(x, b1, actA);
    mid_kernel<512><<<grid, 256, SZM5>>>(actA, 32768,  b2, actB);
    mid_kernel<256><<<grid, 256, SZM2>>>(actB, 294912, b3, actA);
    l4_kernel<<<grid, 256, SZ4>>>(actA, b4, x, out);
}